// round 10
// baseline (speedup 1.0000x reference)
#include <cuda_runtime.h>
#include <cuda_fp16.h>
#include <math.h>

#define TKN 2048
#define BATCH 2
#define SEQ 1024
#define DIMX 1024
#define NH 16
#define NKV 4
#define HD 64
#define KVD (NKV*HD)   // 256
#define NE 8
#define FFX 4096

// ---------------- scratch ----------------
__device__ float g_q [TKN*DIMX];
__device__ float g_k [TKN*KVD];
__device__ float g_v [TKN*KVD];
__device__ float g_x1[TKN*DIMX];
__device__ float g_part[2*TKN*DIMX];
__device__ __half g_h1h [TKN*DIMX];
__device__ __half g_attnh[TKN*DIMX];
__device__ __half g_h2h [TKN*DIMX];
__device__ __half g_hidh[(size_t)NE*TKN*FFX];
__device__ __half g_wq16[DIMX*DIMX];
__device__ __half g_wk16[DIMX*KVD];
__device__ __half g_wv16[DIMX*KVD];
__device__ __half g_wo16[DIMX*DIMX];
__device__ int   g_tok [NE*TKN];
__device__ float g_gate[NE*TKN];
__device__ int   g_dest[NE*TKN];
__device__ int   g_ecnt[NE];
__device__ int   g_counts[NE];

// ---------------- merged fp32->fp16 convert for dense weights + zero ----------------
__device__ __forceinline__ void cvt8(const float* __restrict__ s, __half* __restrict__ d, int i) {
    float4 a = ((const float4*)s)[2*i];
    float4 b = ((const float4*)s)[2*i + 1];
    __half2 h0 = __floats2half2_rn(a.x, a.y);
    __half2 h1 = __floats2half2_rn(a.z, a.w);
    __half2 h2 = __floats2half2_rn(b.x, b.y);
    __half2 h3 = __floats2half2_rn(b.z, b.w);
    uint4 u;
    u.x = ((unsigned)__half_as_ushort(__high2half(h0)) << 16) | __half_as_ushort(__low2half(h0));
    u.y = ((unsigned)__half_as_ushort(__high2half(h1)) << 16) | __half_as_ushort(__low2half(h1));
    u.z = ((unsigned)__half_as_ushort(__high2half(h2)) << 16) | __half_as_ushort(__low2half(h2));
    u.w = ((unsigned)__half_as_ushort(__high2half(h3)) << 16) | __half_as_ushort(__low2half(h3));
    ((uint4*)d)[i] = u;
}

__global__ void cvt4_kernel(const float* __restrict__ wq, const float* __restrict__ wk,
                            const float* __restrict__ wv, const float* __restrict__ wo) {
    int b = blockIdx.x, tid = threadIdx.x;
    if (b == 0 && tid < NE) { g_ecnt[tid] = 0; g_counts[tid] = 0; }
    if (b < 512)       cvt8(wq, g_wq16, b*256 + tid);
    else if (b < 640)  cvt8(wk, g_wk16, (b-512)*256 + tid);
    else if (b < 768)  cvt8(wv, g_wv16, (b-640)*256 + tid);
    else               cvt8(wo, g_wo16, (b-768)*256 + tid);
}

// ---------------- layernorm -> fp16 ----------------
__global__ void ln_kernel(const float* __restrict__ x, const float* __restrict__ g,
                          const float* __restrict__ b, __half* __restrict__ out) {
    int row = blockIdx.x;
    int tid = threadIdx.x;
    const float* xr = x + (size_t)row * DIMX;
    float v[4]; float s = 0.f;
    #pragma unroll
    for (int j = 0; j < 4; j++) { v[j] = xr[tid + 256*j]; s += v[j]; }
    __shared__ float red[8];
    #pragma unroll
    for (int o = 16; o > 0; o >>= 1) s += __shfl_xor_sync(0xffffffffu, s, o);
    if ((tid & 31) == 0) red[tid >> 5] = s;
    __syncthreads();
    float tot = red[0]+red[1]+red[2]+red[3]+red[4]+red[5]+red[6]+red[7];
    float mu = tot / DIMX;
    float sq = 0.f;
    #pragma unroll
    for (int j = 0; j < 4; j++) { float d = v[j]-mu; sq += d*d; }
    #pragma unroll
    for (int o = 16; o > 0; o >>= 1) sq += __shfl_xor_sync(0xffffffffu, sq, o);
    __syncthreads();
    if ((tid & 31) == 0) red[tid >> 5] = sq;
    __syncthreads();
    float vtot = red[0]+red[1]+red[2]+red[3]+red[4]+red[5]+red[6]+red[7];
    float rstd = rsqrtf(vtot / DIMX + 1e-5f);
    #pragma unroll
    for (int j = 0; j < 4; j++) {
        int d = tid + 256*j;
        out[(size_t)row*DIMX + d] = __float2half_rn((v[j]-mu)*rstd*g[d] + b[d]);
    }
}

// ---------------- shared mma macros ----------------
#define LDSM4(R, addr) \
    asm volatile("ldmatrix.sync.aligned.m8n8.x4.shared.b16 {%0,%1,%2,%3}, [%4];" \
        : "=r"(R[0]), "=r"(R[1]), "=r"(R[2]), "=r"(R[3]) : "r"(addr))
#define LDSM4T(R, addr) \
    asm volatile("ldmatrix.sync.aligned.m8n8.x4.trans.shared.b16 {%0,%1,%2,%3}, [%4];" \
        : "=r"(R[0]), "=r"(R[1]), "=r"(R[2]), "=r"(R[3]) : "r"(addr))
#define MMA_F16(C4, A4, B0, B1) \
    asm volatile("mma.sync.aligned.m16n8k16.row.col.f32.f16.f16.f32 " \
        "{%0,%1,%2,%3},{%4,%5,%6,%7},{%8,%9},{%0,%1,%2,%3};" \
        : "+f"(C4[0]), "+f"(C4[1]), "+f"(C4[2]), "+f"(C4[3]) \
        : "r"(A4[0]), "r"(A4[1]), "r"(A4[2]), "r"(A4[3]), "r"(B0), "r"(B1))

// ---------------- dense fp16 GEMM (128x128, warp 64x32, 3-stage) ----------------
// MODE 1: C=A@B+resid (fp32)   MODE 4: fused QKV (fp32 q/k/v)
#define ASTG (128*40)
#define BSTG (32*136)
#define BBASE (3*ASTG)
#define SMEMB ((BBASE + 3*BSTG)*2)

template<int MODE>
__global__ __launch_bounds__(256, 2)
void hgemm(const __half* __restrict__ A, const __half* __restrict__ Bm,
           float* __restrict__ C, const float* __restrict__ resid,
           int M, int N, int K) {
    extern __shared__ __half smh[];
    int ldB = N, ldC = N;
    int n0 = blockIdx.x * 128, cbase = n0;
    if (MODE == 4) {
        if (n0 < DIMX)            { Bm = g_wq16; ldB = DIMX; C = g_q; ldC = DIMX; cbase = n0; }
        else if (n0 < DIMX + KVD) { Bm = g_wk16; ldB = KVD;  C = g_k; ldC = KVD;  cbase = n0 - DIMX; }
        else                      { Bm = g_wv16; ldB = KVD;  C = g_v; ldC = KVD;  cbase = n0 - DIMX - KVD; }
    }
    int m0 = blockIdx.y * 128;
    int tid = threadIdx.x;
    int warp = tid >> 5, lane = tid & 31;
    int wm = warp >> 2, wn = warp & 3;
    int g = lane >> 2, tg = lane & 3;

    const __half* aSrc[2]; unsigned aOff[2];
    #pragma unroll
    for (int p = 0; p < 2; p++) {
        int id = tid + p*256;
        int r = id >> 2, c8 = (id & 3) << 3;
        aSrc[p] = A + (size_t)(m0 + r)*K + c8;
        aOff[p] = (r*40 + c8)*2;
    }
    const __half* bSrc[2]; unsigned bOff[2];
    #pragma unroll
    for (int p = 0; p < 2; p++) {
        int id = tid + p*256;
        int r = id >> 4, c8 = (id & 15) << 3;
        bSrc[p] = Bm + (size_t)r*ldB + cbase + c8;
        bOff[p] = (BBASE + r*136 + c8)*2;
    }
    unsigned smb = (unsigned)__cvta_generic_to_shared(smh);

    auto load_stage = [&](int s, int kt) {
        int k0 = kt*32;
        #pragma unroll
        for (int p = 0; p < 2; p++)
            asm volatile("cp.async.cg.shared.global [%0], [%1], 16;"
                :: "r"(smb + s*(ASTG*2) + aOff[p]), "l"(aSrc[p] + k0));
        #pragma unroll
        for (int p = 0; p < 2; p++)
            asm volatile("cp.async.cg.shared.global [%0], [%1], 16;"
                :: "r"(smb + s*(BSTG*2) + bOff[p]), "l"(bSrc[p] + (size_t)k0*ldB));
        asm volatile("cp.async.commit_group;");
    };

    unsigned aBase = smb + ((wm*64 + ((lane>>3)&1)*8 + (lane&7))*40 + (lane>>4)*8)*2;
    unsigned bBase = smb + BBASE*2 + ((((lane>>3)&1)*8 + (lane&7))*136 + wn*32 + (lane>>4)*8)*2;

    float c[4][4][4] = {};
    int nk = K / 32;
    load_stage(0, 0);
    load_stage(1, 1);
    for (int kt = 0; kt < nk; kt++) {
        int s = kt % 3;
        if (kt < nk - 1) asm volatile("cp.async.wait_group 1;");
        else             asm volatile("cp.async.wait_group 0;");
        __syncthreads();
        unsigned aS = aBase + s*(ASTG*2);
        unsigned bS = bBase + s*(BSTG*2);
        #pragma unroll
        for (int ks = 0; ks < 2; ks++) {
            unsigned af[4][4], bq[2][4];
            #pragma unroll
            for (int i = 0; i < 4; i++)
                LDSM4(af[i], aS + (i*16*40 + ks*16)*2);
            #pragma unroll
            for (int jp = 0; jp < 2; jp++)
                LDSM4T(bq[jp], bS + (ks*16*136 + jp*16)*2);
            #pragma unroll
            for (int i = 0; i < 4; i++)
                #pragma unroll
                for (int j = 0; j < 4; j++)
                    MMA_F16(c[i][j], af[i], bq[j>>1][(j&1)*2], bq[j>>1][(j&1)*2+1]);
        }
        if (kt + 2 < nk) load_stage((kt+2) % 3, kt+2);
    }

    #pragma unroll
    for (int i = 0; i < 4; i++) {
        #pragma unroll
        for (int half = 0; half < 2; half++) {
            int r = m0 + wm*64 + i*16 + g + half*8;
            #pragma unroll
            for (int j = 0; j < 4; j++) {
                float v0 = c[i][j][half*2 + 0];
                float v1 = c[i][j][half*2 + 1];
                int col = cbase + wn*32 + j*8 + 2*tg;
                if (MODE == 4) {
                    *(float2*)&C[(size_t)r*ldC + col] = make_float2(v0, v1);
                } else {
                    float2 rr = *(const float2*)&resid[(size_t)r*ldC + col];
                    *(float2*)&C[(size_t)r*ldC + col] = make_float2(v0+rr.x, v1+rr.y);
                }
            }
        }
    }
}

// ---------------- MoE fp16-A x fp32-B GEMM (128x128, warp 64x32, 3-stage) ----------------
// B loaded fp32 from the ORIGINAL weights (no cvt pass); fragments packed in-register.
// MODE 2: up (gather rows via g_tok, GELU, fp16 out)
// MODE 3: down (scatter*gate, fp32 out -> g_part)
#define B32STG (32*132)                 // floats per B stage
#define B32BASE (3*ASTG*2)              // byte offset of B region (A stages are halves)
#define SMEM32 (B32BASE + 3*B32STG*4)

template<int MODE>
__global__ __launch_bounds__(256, 2)
void hgemm_moe32(const float* __restrict__ Bm, int N, int K) {
    extern __shared__ __half smh[];
    float* smf = (float*)((char*)smh + B32BASE);
    int e = blockIdx.z;
    int M = g_ecnt[e];
    const __half* A; __half* C16 = nullptr; int ldC = N;
    if (MODE == 2) { A = g_h2h; Bm += (size_t)e*DIMX*FFX; C16 = g_hidh + (size_t)e*TKN*FFX; }
    else           { A = g_hidh + (size_t)e*TKN*FFX; Bm += (size_t)e*FFX*DIMX; ldC = DIMX; }
    int m0 = blockIdx.y * 128;
    if (m0 >= M) return;
    int n0 = blockIdx.x * 128;
    int tid = threadIdx.x;
    int warp = tid >> 5, lane = tid & 31;
    int wm = warp >> 2, wn = warp & 3;   // warp tile 64x32
    int g = lane >> 2, tg = lane & 3;

    const __half* aSrc[2]; int aSz[2]; unsigned aOff[2];
    #pragma unroll
    for (int p = 0; p < 2; p++) {
        int id = tid + p*256;
        int r = id >> 2, c8 = (id & 3) << 3;
        int rg = m0 + r;
        bool valid = rg < M;
        const __half* ptr;
        if (MODE == 2) {
            int t = valid ? g_tok[e*TKN + rg] : 0;
            ptr = A + (size_t)t*K + c8;
        } else {
            ptr = A + (size_t)(valid ? rg : 0)*K + c8;
        }
        aSrc[p] = ptr; aSz[p] = valid ? 16 : 0;
        aOff[p] = (r*40 + c8)*2;
    }
    // B fp32 staging: 32 rows x 128 floats = 1024 float4; 4 per thread
    const float* bSrc[4]; unsigned bOff[4];
    #pragma unroll
    for (int p = 0; p < 4; p++) {
        int id = tid + p*256;
        int r = id >> 5, c4 = (id & 31) << 2;
        bSrc[p] = Bm + (size_t)r*N + n0 + c4;
        bOff[p] = B32BASE + (r*132 + c4)*4;
    }
    unsigned smb = (unsigned)__cvta_generic_to_shared(smh);

    auto load_stage = [&](int s, int kt) {
        int k0 = kt*32;
        #pragma unroll
        for (int p = 0; p < 2; p++)
            asm volatile("cp.async.cg.shared.global [%0], [%1], 16, %2;"
                :: "r"(smb + s*(ASTG*2) + aOff[p]), "l"(aSrc[p] + k0), "r"(aSz[p]));
        #pragma unroll
        for (int p = 0; p < 4; p++)
            asm volatile("cp.async.cg.shared.global [%0], [%1], 16;"
                :: "r"(smb + s*(B32STG*4) + bOff[p]), "l"(bSrc[p] + (size_t)k0*N));
        asm volatile("cp.async.commit_group;");
    };

    unsigned aBase = smb + ((wm*64 + ((lane>>3)&1)*8 + (lane&7))*40 + (lane>>4)*8)*2;

    float c[4][4][4] = {};
    int nk = K / 32;
    load_stage(0, 0);
    load_stage(1, 1);
    for (int kt = 0; kt < nk; kt++) {
        int s = kt % 3;
        if (kt < nk - 1) asm volatile("cp.async.wait_group 1;");
        else             asm volatile("cp.async.wait_group 0;");
        __syncthreads();
        unsigned aS = aBase + s*(ASTG*2);
        const float* Bs = smf + s*B32STG;
        #pragma unroll
        for (int ks = 0; ks < 2; ks++) {
            unsigned af[4][4], bf[4][2];
            #pragma unroll
            for (int i = 0; i < 4; i++)
                LDSM4(af[i], aS + (i*16*40 + ks*16)*2);
            #pragma unroll
            for (int j = 0; j < 4; j++) {
                int col = wn*32 + j*8 + g;
                int kr = ks*16 + tg*2;
                float f00 = Bs[(kr  )*132 + col];
                float f01 = Bs[(kr+1)*132 + col];
                float f10 = Bs[(kr+8)*132 + col];
                float f11 = Bs[(kr+9)*132 + col];
                __half2 h0 = __floats2half2_rn(f00, f01);
                __half2 h1 = __floats2half2_rn(f10, f11);
                bf[j][0] = *(unsigned*)&h0;
                bf[j][1] = *(unsigned*)&h1;
            }
            #pragma unroll
            for (int i = 0; i < 4; i++)
                #pragma unroll
                for (int j = 0; j < 4; j++)
                    MMA_F16(c[i][j], af[i], bf[j][0], bf[j][1]);
        }
        if (kt + 2 < nk) load_stage((kt+2) % 3, kt+2);
    }

    #pragma unroll
    for (int i = 0; i < 4; i++) {
        #pragma unroll
        for (int half = 0; half < 2; half++) {
            int r = m0 + wm*64 + i*16 + g + half*8;
            if (r >= M) continue;
            #pragma unroll
            for (int j = 0; j < 4; j++) {
                float v0 = c[i][j][half*2 + 0];
                float v1 = c[i][j][half*2 + 1];
                int col = n0 + wn*32 + j*8 + 2*tg;
                if (MODE == 2) {
                    float o0 = 0.5f*v0*(1.0f + erff(v0*0.70710678118654752f));
                    float o1 = 0.5f*v1*(1.0f + erff(v1*0.70710678118654752f));
                    *(__half2*)&C16[(size_t)r*ldC + col] = __floats2half2_rn(o0, o1);
                } else {
                    int p = g_dest[e*TKN + r];
                    float s = g_gate[e*TKN + r];
                    *(float2*)&g_part[(size_t)p*DIMX + col] = make_float2(s*v0, s*v1);
                }
            }
        }
    }
}

// ---------------- RoPE ----------------
__global__ void rope_kernel() {
    int idx = blockIdx.x*blockDim.x + threadIdx.x;
    const int totq = TKN*NH*32;
    const int totk = TKN*NKV*32;
    float* arr; size_t base; int t, i;
    if (idx < totq) {
        arr = g_q; i = idx & 31; int rest = idx >> 5;
        int head = rest % NH; t = rest / NH;
        base = (size_t)t*DIMX + head*HD;
    } else {
        idx -= totq;
        if (idx >= totk) return;
        arr = g_k; i = idx & 31; int rest = idx >> 5;
        int head = rest % NKV; t = rest / NKV;
        base = (size_t)t*KVD + head*HD;
    }
    int pos = t % SEQ;
    float freq = expf(-(float)(2*i) * (9.210340371976184f / 64.0f));
    float ang = (float)pos * freq;
    float cs = cosf(ang), sn = sinf(ang);
    float x1 = arr[base + i], x2 = arr[base + 32 + i];
    arr[base + i]      = x1*cs - x2*sn;
    arr[base + 32 + i] = x2*cs + x1*sn;
}

// ---------------- tf32 tensor-core flash attention ----------------
#define MMA_TF32(C4, A0,A1,A2,A3, B0,B1) \
    asm volatile("mma.sync.aligned.m16n8k8.row.col.f32.tf32.tf32.f32 " \
        "{%0,%1,%2,%3},{%4,%5,%6,%7},{%8,%9},{%0,%1,%2,%3};" \
        : "+f"(C4[0]), "+f"(C4[1]), "+f"(C4[2]), "+f"(C4[3]) \
        : "r"(A0), "r"(A1), "r"(A2), "r"(A3), "r"(B0), "r"(B1))

#define QSTR 68
#define VSTR 72
#define SM_Q 0
#define SM_K (128*QSTR)
#define SM_V (SM_K + 2*64*QSTR)
#define SM_TOT ((SM_V + 2*64*VSTR)*4)

__device__ __forceinline__ void cpa16(unsigned dst, const float* src) {
    asm volatile("cp.async.cg.shared.global [%0], [%1], 16;" :: "r"(dst), "l"(src));
}

__global__ __launch_bounds__(256, 2)
void attn_mma_kernel() {
    extern __shared__ float sm[];
    int bx = blockIdx.x, h = blockIdx.y, b = blockIdx.z;
    int hk = h >> 2;
    int q0 = bx * 128;
    int tid = threadIdx.x, w = tid >> 5, lane = tid & 31;
    int g = lane >> 2, tg = lane & 3;
    unsigned smbase = (unsigned)__cvta_generic_to_shared(sm);

    #pragma unroll
    for (int p = 0; p < 8; p++) {
        int id = tid + p*256;
        int r = id >> 4, c4 = (id & 15) << 2;
        cpa16(smbase + (SM_Q + r*QSTR + c4)*4,
              g_q + (size_t)(b*SEQ + q0 + r)*DIMX + h*HD + c4);
    }
    auto load_kv = [&](int kt, int bf) {
        #pragma unroll
        for (int p = 0; p < 4; p++) {
            int id = tid + p*256;
            int r = id >> 4, c4 = (id & 15) << 2;
            cpa16(smbase + (SM_K + bf*64*QSTR + r*QSTR + c4)*4,
                  g_k + (size_t)(b*SEQ + kt*64 + r)*KVD + hk*HD + c4);
            cpa16(smbase + (SM_V + bf*64*VSTR + r*VSTR + c4)*4,
                  g_v + (size_t)(b*SEQ + kt*64 + r)*KVD + hk*HD + c4);
        }
    };
    int nkt = 2*bx + 2;
    load_kv(0, 0);
    asm volatile("cp.async.commit_group;");

    int my_last = 2*bx + (w >= 4 ? 1 : 0);
    float m0 = -1.0e30f, m1 = -1.0e30f, l0 = 0.f, l1 = 0.f;
    float o[8][4] = {};
    const float SCALE = 0.18033688011112042f;

    for (int kt = 0; kt < nkt; kt++) {
        int bf = kt & 1;
        if (kt + 1 < nkt) {
            load_kv(kt + 1, bf ^ 1);
            asm volatile("cp.async.commit_group;");
            asm volatile("cp.async.wait_group 1;");
        } else {
            asm volatile("cp.async.wait_group 0;");
        }
        __syncthreads();

        if (kt <= my_last) {
            const float* Qs = sm + SM_Q;
            const float* Ks = sm + SM_K + bf*64*QSTR;
            const float* Vs = sm + SM_V + bf*64*VSTR;
            float s[8][4] = {};
            #pragma unroll
            for (int kk = 0; kk < 8; kk++) {
                int rb = (16*w + g)*QSTR + kk*8;
                unsigned a0 = __float_as_uint(Qs[rb + tg]);
                unsigned a1 = __float_as_uint(Qs[rb + 8*QSTR + tg]);
                unsigned a2 = __float_as_uint(Qs[rb + tg + 4]);
                unsigned a3 = __float_as_uint(Qs[rb + 8*QSTR + tg + 4]);
                #pragma unroll
                for (int j = 0; j < 8; j++) {
                    unsigned b0 = __float_as_uint(Ks[(j*8 + g)*QSTR + kk*8 + tg]);
                    unsigned b1 = __float_as_uint(Ks[(j*8 + g)*QSTR + kk*8 + tg + 4]);
                    MMA_TF32(s[j], a0, a1, a2, a3, b0, b1);
                }
            }
            if (kt == my_last) {
                int r0 = q0 + 16*w + g, r1 = r0 + 8;
                #pragma unroll
                for (int j = 0; j < 8; j++) {
                    int cg = kt*64 + j*8 + 2*tg;
                    s[j][0] = (cg   > r0) ? -1.0e30f : s[j][0]*SCALE;
                    s[j][1] = (cg+1 > r0) ? -1.0e30f : s[j][1]*SCALE;
                    s[j][2] = (cg   > r1) ? -1.0e30f : s[j][2]*SCALE;
                    s[j][3] = (cg+1 > r1) ? -1.0e30f : s[j][3]*SCALE;
                }
            } else {
                #pragma unroll
                for (int j = 0; j < 8; j++)
                    #pragma unroll
                    for (int q = 0; q < 4; q++) s[j][q] *= SCALE;
            }
            float mx0 = -1.0e30f, mx1 = -1.0e30f;
            #pragma unroll
            for (int j = 0; j < 8; j++) {
                mx0 = fmaxf(mx0, fmaxf(s[j][0], s[j][1]));
                mx1 = fmaxf(mx1, fmaxf(s[j][2], s[j][3]));
            }
            mx0 = fmaxf(mx0, __shfl_xor_sync(0xffffffffu, mx0, 1));
            mx0 = fmaxf(mx0, __shfl_xor_sync(0xffffffffu, mx0, 2));
            mx1 = fmaxf(mx1, __shfl_xor_sync(0xffffffffu, mx1, 1));
            mx1 = fmaxf(mx1, __shfl_xor_sync(0xffffffffu, mx1, 2));
            float mn0 = fmaxf(m0, mx0), mn1 = fmaxf(m1, mx1);
            float c0 = exp2f(m0 - mn0), c1 = exp2f(m1 - mn1);
            float rs0 = 0.f, rs1 = 0.f;
            #pragma unroll
            for (int j = 0; j < 8; j++) {
                s[j][0] = exp2f(s[j][0] - mn0); s[j][1] = exp2f(s[j][1] - mn0);
                s[j][2] = exp2f(s[j][2] - mn1); s[j][3] = exp2f(s[j][3] - mn1);
                rs0 += s[j][0] + s[j][1];
                rs1 += s[j][2] + s[j][3];
            }
            rs0 += __shfl_xor_sync(0xffffffffu, rs0, 1);
            rs0 += __shfl_xor_sync(0xffffffffu, rs0, 2);
            rs1 += __shfl_xor_sync(0xffffffffu, rs1, 1);
            rs1 += __shfl_xor_sync(0xffffffffu, rs1, 2);
            l0 = l0*c0 + rs0; l1 = l1*c1 + rs1;
            m0 = mn0; m1 = mn1;
            #pragma unroll
            for (int j = 0; j < 8; j++) {
                o[j][0] *= c0; o[j][1] *= c0;
                o[j][2] *= c1; o[j][3] *= c1;
            }
            int src = (lane & ~3) | (tg >> 1);
            #pragma unroll
            for (int kk = 0; kk < 8; kk++) {
                float v0 = __shfl_sync(0xffffffffu, s[kk][0], src);
                float v1 = __shfl_sync(0xffffffffu, s[kk][1], src);
                float v2 = __shfl_sync(0xffffffffu, s[kk][2], src);
                float v3 = __shfl_sync(0xffffffffu, s[kk][3], src);
                float u0 = __shfl_sync(0xffffffffu, s[kk][0], src + 2);
                float u1 = __shfl_sync(0xffffffffu, s[kk][1], src + 2);
                float u2 = __shfl_sync(0xffffffffu, s[kk][2], src + 2);
                float u3 = __shfl_sync(0xffffffffu, s[kk][3], src + 2);
                bool odd = tg & 1;
                unsigned a0 = __float_as_uint(odd ? v1 : v0);
                unsigned a1 = __float_as_uint(odd ? v3 : v2);
                unsigned a2 = __float_as_uint(odd ? u1 : u0);
                unsigned a3 = __float_as_uint(odd ? u3 : u2);
                #pragma unroll
                for (int j = 0; j < 8; j++) {
                    unsigned b0 = __float_as_uint(Vs[(kk*8 + tg)*VSTR + j*8 + g]);
                    unsigned b1 = __float_as_uint(Vs[(kk*8 + tg + 4)*VSTR + j*8 + g]);
                    MMA_TF32(o[j], a0, a1, a2, a3, b0, b1);
                }
            }
        }
        __syncthreads();
    }

    float i0 = 1.0f / l0, i1 = 1.0f / l1;
    size_t r0b = (size_t)(b*SEQ + q0 + 16*w + g    )*DIMX + h*HD;
    size_t r1b = (size_t)(b*SEQ + q0 + 16*w + g + 8)*DIMX + h*HD;
    #pragma unroll
    for (int j = 0; j < 8; j++) {
        int col = j*8 + 2*tg;
        *(__half2*)&g_attnh[r0b + col] = __floats2half2_rn(o[j][0]*i0, o[j][1]*i0);
        *(__half2*)&g_attnh[r1b + col] = __floats2half2_rn(o[j][2]*i1, o[j][3]*i1);
    }
}

// ---------------- router ----------------
__global__ void router_kernel(const float* __restrict__ wg) {
    int warp = (blockIdx.x*blockDim.x + threadIdx.x) >> 5;
    int lane = threadIdx.x & 31;
    if (warp >= TKN) return;
    int t = warp;
    float acc[NE] = {};
    const __half* hr = g_h2h + (size_t)t*DIMX;
    for (int d = lane; d < DIMX; d += 32) {
        float hv = __half2float(hr[d]);
        const float* wr = wg + (size_t)d*NE;
        #pragma unroll
        for (int e = 0; e < NE; e++) acc[e] += hv * wr[e];
    }
    #pragma unroll
    for (int e = 0; e < NE; e++)
        #pragma unroll
        for (int off = 16; off > 0; off >>= 1)
            acc[e] += __shfl_xor_sync(0xffffffffu, acc[e], off);
    if (lane == 0) {
        int e0 = 0; float v0 = acc[0];
        #pragma unroll
        for (int e = 1; e < NE; e++) if (acc[e] > v0) { v0 = acc[e]; e0 = e; }
        int e1 = -1; float v1 = -3.4e38f;
        #pragma unroll
        for (int e = 0; e < NE; e++) if (e != e0 && acc[e] > v1) { v1 = acc[e]; e1 = e; }
        float ex = expf(v1 - v0);
        float den = 1.0f + ex;
        float gg0 = 1.0f/den, gg1 = ex/den;
        atomicAdd(&g_counts[e0], 1); atomicAdd(&g_counts[e1], 1);
        int p0 = atomicAdd(&g_ecnt[e0], 1);
        g_tok[e0*TKN+p0] = t; g_gate[e0*TKN+p0] = gg0; g_dest[e0*TKN+p0] = t;
        int p1 = atomicAdd(&g_ecnt[e1], 1);
        g_tok[e1*TKN+p1] = t; g_gate[e1*TKN+p1] = gg1; g_dest[e1*TKN+p1] = TKN + t;
    }
}

__global__ void combine_kernel(float* __restrict__ out) {
    int i = blockIdx.x*256 + threadIdx.x;
    out[i] = g_x1[i] + g_part[i] + g_part[TKN*DIMX + i];
}

__global__ void lb_kernel(float* __restrict__ out, int out_size) {
    if (threadIdx.x == 0) {
        float tot = 0.f;
        for (int e = 0; e < NE; e++) tot += (float)g_counts[e];
        float loss = 0.f;
        for (int e = 0; e < NE; e++) {
            float cn = (float)g_counts[e]/tot - 1.0f/NE;
            loss += cn*cn;
        }
        out[out_size - 1] = loss / NE;
    }
}

// ---------------- launch ----------------
extern "C" void kernel_launch(void* const* d_in, const int* in_sizes, int n_in,
                              void* d_out, int out_size) {
    const float* x    = (const float*)d_in[0];
    const float* wq   = (const float*)d_in[1];
    const float* wk   = (const float*)d_in[2];
    const float* wv   = (const float*)d_in[3];
    const float* wo   = (const float*)d_in[4];
    const float* wg   = (const float*)d_in[5];
    const float* w1   = (const float*)d_in[6];
    const float* w2   = (const float*)d_in[7];
    const float* ln1g = (const float*)d_in[8];
    const float* ln1b = (const float*)d_in[9];
    const float* ln2g = (const float*)d_in[10];
    const float* ln2b = (const float*)d_in[11];
    float* out = (float*)d_out;

    float *p_x1;
    __half *p_h1h, *p_attnh, *p_h2h, *p_wo16;
    cudaGetSymbolAddress((void**)&p_x1,   g_x1);
    cudaGetSymbolAddress((void**)&p_h1h,  g_h1h);
    cudaGetSymbolAddress((void**)&p_attnh,g_attnh);
    cudaGetSymbolAddress((void**)&p_h2h,  g_h2h);
    cudaGetSymbolAddress((void**)&p_wo16, g_wo16);

    static int attr_set = 0;
    if (!attr_set) {
        cudaFuncSetAttribute(attn_mma_kernel,
                             cudaFuncAttributeMaxDynamicSharedMemorySize, SM_TOT);
        cudaFuncSetAttribute(hgemm<1>, cudaFuncAttributeMaxDynamicSharedMemorySize, SMEMB);
        cudaFuncSetAttribute(hgemm<4>, cudaFuncAttributeMaxDynamicSharedMemorySize, SMEMB);
        cudaFuncSetAttribute(hgemm_moe32<2>, cudaFuncAttributeMaxDynamicSharedMemorySize, SMEM32);
        cudaFuncSetAttribute(hgemm_moe32<3>, cudaFuncAttributeMaxDynamicSharedMemorySize, SMEM32);
        attr_set = 1;
    }

    // dense weight converts (+ expert-counter zeroing), one launch
    cvt4_kernel<<<1280, 256>>>(wq, wk, wv, wo);

    ln_kernel<<<TKN, 256>>>(x, ln1g, ln1b, p_h1h);

    hgemm<4><<<dim3((DIMX+2*KVD)/128, TKN/128, 1), 256, SMEMB>>>(
        p_h1h, nullptr, nullptr, nullptr, TKN, DIMX, DIMX);

    rope_kernel<<<(TKN*(NH+NKV)*32)/256, 256>>>();
    attn_mma_kernel<<<dim3(SEQ/128, NH, BATCH), 256, SM_TOT>>>();

    hgemm<1><<<dim3(DIMX/128, TKN/128, 1), 256, SMEMB>>>(
        p_attnh, p_wo16, p_x1, x, TKN, DIMX, DIMX);
    ln_kernel<<<TKN, 256>>>(p_x1, ln2g, ln2b, p_h2h);

    router_kernel<<<TKN/8, 256>>>(wg);

    // MoE GEMMs read fp32 weights directly (no cvt pass)
    hgemm_moe32<2><<<dim3(FFX/128,  TKN/128, NE), 256, SMEM32>>>(w1, FFX, DIMX);
    hgemm_moe32<3><<<dim3(DIMX/128, TKN/128, NE), 256, SMEM32>>>(w2, DIMX, FFX);

    combine_kernel<<<(TKN*DIMX)/256, 256>>>(out);
    lb_kernel<<<1, 32>>>(out, out_size);
}

// round 11
// speedup vs baseline: 1.1004x; 1.1004x over previous
#include <cuda_runtime.h>
#include <cuda_fp16.h>
#include <math.h>

#define TKN 2048
#define BATCH 2
#define SEQ 1024
#define DIMX 1024
#define NH 16
#define NKV 4
#define HD 64
#define KVD (NKV*HD)   // 256
#define NE 8
#define FFX 4096

// ---------------- scratch ----------------
__device__ float g_x1[TKN*DIMX];
__device__ float g_part[2*TKN*DIMX];
__device__ __half g_qh [TKN*DIMX];
__device__ __half g_kh [TKN*KVD];
__device__ __half g_vh [TKN*KVD];
__device__ __half g_h1h [TKN*DIMX];
__device__ __half g_attnh[TKN*DIMX];
__device__ __half g_h2h [TKN*DIMX];
__device__ __half g_hidh[(size_t)NE*TKN*FFX];
__device__ __half g_wq16[DIMX*DIMX];
__device__ __half g_wk16[DIMX*KVD];
__device__ __half g_wv16[DIMX*KVD];
__device__ __half g_wo16[DIMX*DIMX];
__device__ __half g_w116[(size_t)NE*DIMX*FFX];
__device__ __half g_w216[(size_t)NE*FFX*DIMX];
__device__ int   g_tok [NE*TKN];
__device__ float g_gate[NE*TKN];
__device__ int   g_dest[NE*TKN];
__device__ int   g_ecnt[NE];
__device__ int   g_counts[NE];

__global__ void zero_kernel() {
    int i = threadIdx.x;
    if (i < NE) { g_ecnt[i] = 0; g_counts[i] = 0; }
}

// ---------------- fp32 -> fp16 convert ----------------
__global__ void cvt_kernel(const float* __restrict__ s, __half* __restrict__ d, int n8) {
    int i = blockIdx.x*256 + threadIdx.x;
    if (i >= n8) return;
    float4 a = ((const float4*)s)[2*i];
    float4 b = ((const float4*)s)[2*i + 1];
    __half2 h0 = __floats2half2_rn(a.x, a.y);
    __half2 h1 = __floats2half2_rn(a.z, a.w);
    __half2 h2 = __floats2half2_rn(b.x, b.y);
    __half2 h3 = __floats2half2_rn(b.z, b.w);
    uint4 u;
    u.x = ((unsigned)__half_as_ushort(__high2half(h0)) << 16) | __half_as_ushort(__low2half(h0));
    u.y = ((unsigned)__half_as_ushort(__high2half(h1)) << 16) | __half_as_ushort(__low2half(h1));
    u.z = ((unsigned)__half_as_ushort(__high2half(h2)) << 16) | __half_as_ushort(__low2half(h2));
    u.w = ((unsigned)__half_as_ushort(__high2half(h3)) << 16) | __half_as_ushort(__low2half(h3));
    ((uint4*)d)[i] = u;
}

// ---------------- layernorm -> fp16 ----------------
__global__ void ln_kernel(const float* __restrict__ x, const float* __restrict__ g,
                          const float* __restrict__ b, __half* __restrict__ out) {
    int row = blockIdx.x;
    int tid = threadIdx.x;
    const float* xr = x + (size_t)row * DIMX;
    float v[4]; float s = 0.f;
    #pragma unroll
    for (int j = 0; j < 4; j++) { v[j] = xr[tid + 256*j]; s += v[j]; }
    __shared__ float red[8];
    #pragma unroll
    for (int o = 16; o > 0; o >>= 1) s += __shfl_xor_sync(0xffffffffu, s, o);
    if ((tid & 31) == 0) red[tid >> 5] = s;
    __syncthreads();
    float tot = red[0]+red[1]+red[2]+red[3]+red[4]+red[5]+red[6]+red[7];
    float mu = tot / DIMX;
    float sq = 0.f;
    #pragma unroll
    for (int j = 0; j < 4; j++) { float d = v[j]-mu; sq += d*d; }
    #pragma unroll
    for (int o = 16; o > 0; o >>= 1) sq += __shfl_xor_sync(0xffffffffu, sq, o);
    __syncthreads();
    if ((tid & 31) == 0) red[tid >> 5] = sq;
    __syncthreads();
    float vtot = red[0]+red[1]+red[2]+red[3]+red[4]+red[5]+red[6]+red[7];
    float rstd = rsqrtf(vtot / DIMX + 1e-5f);
    #pragma unroll
    for (int j = 0; j < 4; j++) {
        int d = tid + 256*j;
        out[(size_t)row*DIMX + d] = __float2half_rn((v[j]-mu)*rstd*g[d] + b[d]);
    }
}

// ---------------- shared mma macros ----------------
#define LDSM4(R, addr) \
    asm volatile("ldmatrix.sync.aligned.m8n8.x4.shared.b16 {%0,%1,%2,%3}, [%4];" \
        : "=r"(R[0]), "=r"(R[1]), "=r"(R[2]), "=r"(R[3]) : "r"(addr))
#define LDSM4T(R, addr) \
    asm volatile("ldmatrix.sync.aligned.m8n8.x4.trans.shared.b16 {%0,%1,%2,%3}, [%4];" \
        : "=r"(R[0]), "=r"(R[1]), "=r"(R[2]), "=r"(R[3]) : "r"(addr))
#define MMA_F16(C4, A4, B0, B1) \
    asm volatile("mma.sync.aligned.m16n8k16.row.col.f32.f16.f16.f32 " \
        "{%0,%1,%2,%3},{%4,%5,%6,%7},{%8,%9},{%0,%1,%2,%3};" \
        : "+f"(C4[0]), "+f"(C4[1]), "+f"(C4[2]), "+f"(C4[3]) \
        : "r"(A4[0]), "r"(A4[1]), "r"(A4[2]), "r"(A4[3]), "r"(B0), "r"(B1))

// ---------------- fp16 tensor-core GEMM (m16n8k16, ldmatrix, 3-stage) ----------------
// MODE 1: C=A@B+resid (fp32 out)  MODE 2: MoE up (gather, GELU, fp16 out)
// MODE 3: MoE down (scatter*gate, fp32)  MODE 4: fused QKV (fp16 q/k/v out)
#define ASTG (128*40)
#define BSTG (32*136)
#define BBASE (3*ASTG)
#define SMEMB ((BBASE + 3*BSTG)*2)

template<int MODE>
__global__ __launch_bounds__(256, 2)
void hgemm(const __half* __restrict__ A, const __half* __restrict__ Bm,
           float* __restrict__ C, const float* __restrict__ resid,
           int M, int N, int K) {
    extern __shared__ __half smh[];
    int e = blockIdx.z;
    int ldB = N, ldC = N;
    int n0 = blockIdx.x * 128, cbase = n0;
    __half* C16 = nullptr;
    if (MODE == 2) { M = g_ecnt[e]; A = g_h2h; Bm = g_w116 + (size_t)e*DIMX*FFX; C16 = g_hidh + (size_t)e*TKN*FFX; }
    if (MODE == 3) { M = g_ecnt[e]; A = g_hidh + (size_t)e*TKN*FFX; Bm = g_w216 + (size_t)e*FFX*DIMX; ldC = DIMX; }
    if (MODE == 4) {
        if (n0 < DIMX)            { Bm = g_wq16; ldB = DIMX; C16 = g_qh; ldC = DIMX; cbase = n0; }
        else if (n0 < DIMX + KVD) { Bm = g_wk16; ldB = KVD;  C16 = g_kh; ldC = KVD;  cbase = n0 - DIMX; }
        else                      { Bm = g_wv16; ldB = KVD;  C16 = g_vh; ldC = KVD;  cbase = n0 - DIMX - KVD; }
    }
    int m0 = blockIdx.y * 128;
    if (m0 >= M) return;
    int tid = threadIdx.x;
    int warp = tid >> 5, lane = tid & 31;
    int wm = warp >> 2, wn = warp & 3;   // warp tile 64x32
    int g = lane >> 2, tg = lane & 3;

    const __half* aSrc[2]; int aSz[2]; unsigned aOff[2];
    #pragma unroll
    for (int p = 0; p < 2; p++) {
        int id = tid + p*256;
        int r = id >> 2, c8 = (id & 3) << 3;
        int rg = m0 + r;
        bool valid = rg < M;
        const __half* ptr;
        if (MODE == 2) {
            int t = valid ? g_tok[e*TKN + rg] : 0;
            ptr = A + (size_t)t*K + c8;
        } else {
            ptr = A + (size_t)(valid ? rg : 0)*K + c8;
        }
        aSrc[p] = ptr; aSz[p] = valid ? 16 : 0;
        aOff[p] = (r*40 + c8)*2;
    }
    const __half* bSrc[2]; unsigned bOff[2];
    #pragma unroll
    for (int p = 0; p < 2; p++) {
        int id = tid + p*256;
        int r = id >> 4, c8 = (id & 15) << 3;
        bSrc[p] = Bm + (size_t)r*ldB + cbase + c8;
        bOff[p] = (BBASE + r*136 + c8)*2;
    }
    unsigned smb = (unsigned)__cvta_generic_to_shared(smh);

    auto load_stage = [&](int s, int kt) {
        int k0 = kt*32;
        #pragma unroll
        for (int p = 0; p < 2; p++)
            asm volatile("cp.async.cg.shared.global [%0], [%1], 16, %2;"
                :: "r"(smb + s*(ASTG*2) + aOff[p]), "l"(aSrc[p] + k0), "r"(aSz[p]));
        #pragma unroll
        for (int p = 0; p < 2; p++)
            asm volatile("cp.async.cg.shared.global [%0], [%1], 16;"
                :: "r"(smb + s*(BSTG*2) + bOff[p]), "l"(bSrc[p] + (size_t)k0*ldB));
        asm volatile("cp.async.commit_group;");
    };

    unsigned aBase = smb + ((wm*64 + ((lane>>3)&1)*8 + (lane&7))*40 + (lane>>4)*8)*2;
    unsigned bBase = smb + BBASE*2 + ((((lane>>3)&1)*8 + (lane&7))*136 + wn*32 + (lane>>4)*8)*2;

    float c[4][4][4] = {};
    int nk = K / 32;
    load_stage(0, 0);
    load_stage(1, 1);
    for (int kt = 0; kt < nk; kt++) {
        int s = kt % 3;
        if (kt < nk - 1) asm volatile("cp.async.wait_group 1;");
        else             asm volatile("cp.async.wait_group 0;");
        __syncthreads();
        unsigned aS = aBase + s*(ASTG*2);
        unsigned bS = bBase + s*(BSTG*2);
        #pragma unroll
        for (int ks = 0; ks < 2; ks++) {
            unsigned af[4][4], bq[2][4];
            #pragma unroll
            for (int i = 0; i < 4; i++)
                LDSM4(af[i], aS + (i*16*40 + ks*16)*2);
            #pragma unroll
            for (int jp = 0; jp < 2; jp++)
                LDSM4T(bq[jp], bS + (ks*16*136 + jp*16)*2);
            #pragma unroll
            for (int i = 0; i < 4; i++)
                #pragma unroll
                for (int j = 0; j < 4; j++)
                    MMA_F16(c[i][j], af[i], bq[j>>1][(j&1)*2], bq[j>>1][(j&1)*2+1]);
        }
        if (kt + 2 < nk) load_stage((kt+2) % 3, kt+2);
    }

    #pragma unroll
    for (int i = 0; i < 4; i++) {
        #pragma unroll
        for (int half = 0; half < 2; half++) {
            int r = m0 + wm*64 + i*16 + g + half*8;
            if ((MODE == 2 || MODE == 3) && r >= M) continue;
            #pragma unroll
            for (int j = 0; j < 4; j++) {
                float v0 = c[i][j][half*2 + 0];
                float v1 = c[i][j][half*2 + 1];
                int col = cbase + wn*32 + j*8 + 2*tg;
                if (MODE == 4) {
                    *(__half2*)&C16[(size_t)r*ldC + col] = __floats2half2_rn(v0, v1);
                } else if (MODE == 1) {
                    float2 rr = *(const float2*)&resid[(size_t)r*ldC + col];
                    *(float2*)&C[(size_t)r*ldC + col] = make_float2(v0+rr.x, v1+rr.y);
                } else if (MODE == 2) {
                    float o0 = 0.5f*v0*(1.0f + erff(v0*0.70710678118654752f));
                    float o1 = 0.5f*v1*(1.0f + erff(v1*0.70710678118654752f));
                    *(__half2*)&C16[(size_t)r*ldC + col] = __floats2half2_rn(o0, o1);
                } else {
                    int p = g_dest[e*TKN + r];
                    float s = g_gate[e*TKN + r];
                    *(float2*)&g_part[(size_t)p*DIMX + col] = make_float2(s*v0, s*v1);
                }
            }
        }
    }
}

// ---------------- RoPE (fp16 in place) ----------------
__global__ void rope_kernel() {
    int idx = blockIdx.x*blockDim.x + threadIdx.x;
    const int totq = TKN*NH*32;
    const int totk = TKN*NKV*32;
    __half* arr; size_t base; int t, i;
    if (idx < totq) {
        arr = g_qh; i = idx & 31; int rest = idx >> 5;
        int head = rest % NH; t = rest / NH;
        base = (size_t)t*DIMX + head*HD;
    } else {
        idx -= totq;
        if (idx >= totk) return;
        arr = g_kh; i = idx & 31; int rest = idx >> 5;
        int head = rest % NKV; t = rest / NKV;
        base = (size_t)t*KVD + head*HD;
    }
    int pos = t % SEQ;
    float freq = expf(-(float)(2*i) * (9.210340371976184f / 64.0f));
    float ang = (float)pos * freq;
    float cs = cosf(ang), sn = sinf(ang);
    float x1 = __half2float(arr[base + i]), x2 = __half2float(arr[base + 32 + i]);
    arr[base + i]      = __float2half_rn(x1*cs - x2*sn);
    arr[base + 32 + i] = __float2half_rn(x2*cs + x1*sn);
}

// ---------------- fp16 tensor-core flash attention (shuffle-free P@V) ----------------
#define FSTR 72                      // halves; 144B stride -> ldmatrix conflict-free
#define FSM_Q 0
#define FSM_K (128*FSTR)
#define FSM_V (FSM_K + 2*64*FSTR)
#define FSM_TOT ((FSM_V + 2*64*FSTR)*2)

__global__ __launch_bounds__(256, 2)
void attn_f16_kernel() {
    extern __shared__ __half smA[];
    int bx = blockIdx.x, h = blockIdx.y, b = blockIdx.z;
    int hk = h >> 2;
    int q0 = bx * 128;
    int tid = threadIdx.x, w = tid >> 5, lane = tid & 31;
    int g = lane >> 2, tg = lane & 3;
    unsigned smb = (unsigned)__cvta_generic_to_shared(smA);
    int lrow = (lane & 7) + ((lane >> 3) & 1)*8;
    int lcol8 = (lane >> 4)*8;

    // Q load: 128 rows x 64 halves (8x16B chunks/row)
    #pragma unroll
    for (int p = 0; p < 4; p++) {
        int id = tid + p*256;
        int r = id >> 3, c8 = (id & 7) << 3;
        asm volatile("cp.async.cg.shared.global [%0], [%1], 16;"
            :: "r"(smb + (FSM_Q + r*FSTR + c8)*2),
               "l"(g_qh + (size_t)(b*SEQ + q0 + r)*DIMX + h*HD + c8));
    }
    auto load_kv = [&](int kt, int bf) {
        #pragma unroll
        for (int p = 0; p < 2; p++) {
            int id = tid + p*256;
            int r = id >> 3, c8 = (id & 7) << 3;
            asm volatile("cp.async.cg.shared.global [%0], [%1], 16;"
                :: "r"(smb + (FSM_K + bf*64*FSTR + r*FSTR + c8)*2),
                   "l"(g_kh + (size_t)(b*SEQ + kt*64 + r)*KVD + hk*HD + c8));
            asm volatile("cp.async.cg.shared.global [%0], [%1], 16;"
                :: "r"(smb + (FSM_V + bf*64*FSTR + r*FSTR + c8)*2),
                   "l"(g_vh + (size_t)(b*SEQ + kt*64 + r)*KVD + hk*HD + c8));
        }
    };
    int nkt = 2*bx + 2;
    load_kv(0, 0);
    asm volatile("cp.async.commit_group;");

    int my_last = 2*bx + (w >= 4 ? 1 : 0);
    float m0 = -1.0e30f, m1 = -1.0e30f, l0 = 0.f, l1 = 0.f;
    float o[8][4] = {};
    const float SCALE = 0.18033688011112042f;  // (1/8)*log2(e)

    unsigned qBase = smb + ((FSM_Q + (16*w + lrow)*FSTR) + lcol8)*2;

    for (int kt = 0; kt < nkt; kt++) {
        int bf = kt & 1;
        if (kt + 1 < nkt) {
            load_kv(kt + 1, bf ^ 1);
            asm volatile("cp.async.commit_group;");
            asm volatile("cp.async.wait_group 1;");
        } else {
            asm volatile("cp.async.wait_group 0;");
        }
        __syncthreads();

        if (kt <= my_last) {
            unsigned kBase = smb + ((FSM_K + bf*64*FSTR + lrow*FSTR) + lcol8)*2;
            unsigned vBase = smb + ((FSM_V + bf*64*FSTR + lrow*FSTR) + lcol8)*2;

            // S = Q @ K^T : K stored [key][d] row-major, plain LDSM gives B-frags
            float s[8][4] = {};
            #pragma unroll
            for (int ks = 0; ks < 4; ks++) {
                unsigned af[4], kb[4][4];
                LDSM4(af, qBase + ks*32);
                #pragma unroll
                for (int j2 = 0; j2 < 4; j2++)
                    LDSM4(kb[j2], kBase + (j2*16*FSTR)*2 + ks*32);
                #pragma unroll
                for (int j = 0; j < 8; j++)
                    MMA_F16(s[j], af, kb[j>>1][j&1], kb[j>>1][(j&1)+2]);
            }
            // scale + causal mask
            if (kt == my_last) {
                int r0 = q0 + 16*w + g, r1 = r0 + 8;
                #pragma unroll
                for (int j = 0; j < 8; j++) {
                    int cg = kt*64 + j*8 + 2*tg;
                    s[j][0] = (cg   > r0) ? -1.0e30f : s[j][0]*SCALE;
                    s[j][1] = (cg+1 > r0) ? -1.0e30f : s[j][1]*SCALE;
                    s[j][2] = (cg   > r1) ? -1.0e30f : s[j][2]*SCALE;
                    s[j][3] = (cg+1 > r1) ? -1.0e30f : s[j][3]*SCALE;
                }
            } else {
                #pragma unroll
                for (int j = 0; j < 8; j++)
                    #pragma unroll
                    for (int q = 0; q < 4; q++) s[j][q] *= SCALE;
            }
            // online softmax (rows g and g+8; quad = lanes tg 0..3)
            float mx0 = -1.0e30f, mx1 = -1.0e30f;
            #pragma unroll
            for (int j = 0; j < 8; j++) {
                mx0 = fmaxf(mx0, fmaxf(s[j][0], s[j][1]));
                mx1 = fmaxf(mx1, fmaxf(s[j][2], s[j][3]));
            }
            mx0 = fmaxf(mx0, __shfl_xor_sync(0xffffffffu, mx0, 1));
            mx0 = fmaxf(mx0, __shfl_xor_sync(0xffffffffu, mx0, 2));
            mx1 = fmaxf(mx1, __shfl_xor_sync(0xffffffffu, mx1, 1));
            mx1 = fmaxf(mx1, __shfl_xor_sync(0xffffffffu, mx1, 2));
            float mn0 = fmaxf(m0, mx0), mn1 = fmaxf(m1, mx1);
            float c0 = exp2f(m0 - mn0), c1 = exp2f(m1 - mn1);
            float rs0 = 0.f, rs1 = 0.f;
            #pragma unroll
            for (int j = 0; j < 8; j++) {
                s[j][0] = exp2f(s[j][0] - mn0); s[j][1] = exp2f(s[j][1] - mn0);
                s[j][2] = exp2f(s[j][2] - mn1); s[j][3] = exp2f(s[j][3] - mn1);
                rs0 += s[j][0] + s[j][1];
                rs1 += s[j][2] + s[j][3];
            }
            rs0 += __shfl_xor_sync(0xffffffffu, rs0, 1);
            rs0 += __shfl_xor_sync(0xffffffffu, rs0, 2);
            rs1 += __shfl_xor_sync(0xffffffffu, rs1, 1);
            rs1 += __shfl_xor_sync(0xffffffffu, rs1, 2);
            l0 = l0*c0 + rs0; l1 = l1*c1 + rs1;
            m0 = mn0; m1 = mn1;
            #pragma unroll
            for (int j = 0; j < 8; j++) {
                o[j][0] *= c0; o[j][1] *= c0;
                o[j][2] *= c1; o[j][3] *= c1;
            }
            // P @ V : A-frags straight from accumulators (NO shuffles)
            #pragma unroll
            for (int kk = 0; kk < 4; kk++) {
                __half2 p0 = __floats2half2_rn(s[2*kk  ][0], s[2*kk  ][1]);
                __half2 p1 = __floats2half2_rn(s[2*kk  ][2], s[2*kk  ][3]);
                __half2 p2 = __floats2half2_rn(s[2*kk+1][0], s[2*kk+1][1]);
                __half2 p3 = __floats2half2_rn(s[2*kk+1][2], s[2*kk+1][3]);
                unsigned pa[4] = { *(unsigned*)&p0, *(unsigned*)&p1,
                                   *(unsigned*)&p2, *(unsigned*)&p3 };
                #pragma unroll
                for (int j2 = 0; j2 < 4; j2++) {
                    unsigned vb[4];
                    LDSM4T(vb, vBase + (kk*16*FSTR + j2*16)*2);
                    MMA_F16(o[2*j2  ], pa, vb[0], vb[1]);
                    MMA_F16(o[2*j2+1], pa, vb[2], vb[3]);
                }
            }
        }
        __syncthreads();
    }

    float i0 = 1.0f / l0, i1 = 1.0f / l1;
    size_t r0b = (size_t)(b*SEQ + q0 + 16*w + g    )*DIMX + h*HD;
    size_t r1b = (size_t)(b*SEQ + q0 + 16*w + g + 8)*DIMX + h*HD;
    #pragma unroll
    for (int j = 0; j < 8; j++) {
        int col = j*8 + 2*tg;
        *(__half2*)&g_attnh[r0b + col] = __floats2half2_rn(o[j][0]*i0, o[j][1]*i0);
        *(__half2*)&g_attnh[r1b + col] = __floats2half2_rn(o[j][2]*i1, o[j][3]*i1);
    }
}

// ---------------- router ----------------
__global__ void router_kernel(const float* __restrict__ wg) {
    int warp = (blockIdx.x*blockDim.x + threadIdx.x) >> 5;
    int lane = threadIdx.x & 31;
    if (warp >= TKN) return;
    int t = warp;
    float acc[NE] = {};
    const __half* hr = g_h2h + (size_t)t*DIMX;
    for (int d = lane; d < DIMX; d += 32) {
        float hv = __half2float(hr[d]);
        const float* wr = wg + (size_t)d*NE;
        #pragma unroll
        for (int e = 0; e < NE; e++) acc[e] += hv * wr[e];
    }
    #pragma unroll
    for (int e = 0; e < NE; e++)
        #pragma unroll
        for (int off = 16; off > 0; off >>= 1)
            acc[e] += __shfl_xor_sync(0xffffffffu, acc[e], off);
    if (lane == 0) {
        int e0 = 0; float v0 = acc[0];
        #pragma unroll
        for (int e = 1; e < NE; e++) if (acc[e] > v0) { v0 = acc[e]; e0 = e; }
        int e1 = -1; float v1 = -3.4e38f;
        #pragma unroll
        for (int e = 0; e < NE; e++) if (e != e0 && acc[e] > v1) { v1 = acc[e]; e1 = e; }
        float ex = expf(v1 - v0);
        float den = 1.0f + ex;
        float gg0 = 1.0f/den, gg1 = ex/den;
        atomicAdd(&g_counts[e0], 1); atomicAdd(&g_counts[e1], 1);
        int p0 = atomicAdd(&g_ecnt[e0], 1);
        g_tok[e0*TKN+p0] = t; g_gate[e0*TKN+p0] = gg0; g_dest[e0*TKN+p0] = t;
        int p1 = atomicAdd(&g_ecnt[e1], 1);
        g_tok[e1*TKN+p1] = t; g_gate[e1*TKN+p1] = gg1; g_dest[e1*TKN+p1] = TKN + t;
    }
}

__global__ void combine_kernel(float* __restrict__ out) {
    int i = blockIdx.x*256 + threadIdx.x;
    out[i] = g_x1[i] + g_part[i] + g_part[TKN*DIMX + i];
}

__global__ void lb_kernel(float* __restrict__ out, int out_size) {
    if (threadIdx.x == 0) {
        float tot = 0.f;
        for (int e = 0; e < NE; e++) tot += (float)g_counts[e];
        float loss = 0.f;
        for (int e = 0; e < NE; e++) {
            float cn = (float)g_counts[e]/tot - 1.0f/NE;
            loss += cn*cn;
        }
        out[out_size - 1] = loss / NE;
    }
}

// ---------------- launch ----------------
extern "C" void kernel_launch(void* const* d_in, const int* in_sizes, int n_in,
                              void* d_out, int out_size) {
    const float* x    = (const float*)d_in[0];
    const float* wq   = (const float*)d_in[1];
    const float* wk   = (const float*)d_in[2];
    const float* wv   = (const float*)d_in[3];
    const float* wo   = (const float*)d_in[4];
    const float* wg   = (const float*)d_in[5];
    const float* w1   = (const float*)d_in[6];
    const float* w2   = (const float*)d_in[7];
    const float* ln1g = (const float*)d_in[8];
    const float* ln1b = (const float*)d_in[9];
    const float* ln2g = (const float*)d_in[10];
    const float* ln2b = (const float*)d_in[11];
    float* out = (float*)d_out;

    float *p_x1;
    __half *p_h1h, *p_attnh, *p_h2h;
    __half *p_wq16, *p_wk16, *p_wv16, *p_wo16, *p_w116, *p_w216;
    cudaGetSymbolAddress((void**)&p_x1,   g_x1);
    cudaGetSymbolAddress((void**)&p_h1h,  g_h1h);
    cudaGetSymbolAddress((void**)&p_attnh,g_attnh);
    cudaGetSymbolAddress((void**)&p_h2h,  g_h2h);
    cudaGetSymbolAddress((void**)&p_wq16, g_wq16);
    cudaGetSymbolAddress((void**)&p_wk16, g_wk16);
    cudaGetSymbolAddress((void**)&p_wv16, g_wv16);
    cudaGetSymbolAddress((void**)&p_wo16, g_wo16);
    cudaGetSymbolAddress((void**)&p_w116, g_w116);
    cudaGetSymbolAddress((void**)&p_w216, g_w216);

    static int attr_set = 0;
    if (!attr_set) {
        cudaFuncSetAttribute(attn_f16_kernel,
                             cudaFuncAttributeMaxDynamicSharedMemorySize, FSM_TOT);
        cudaFuncSetAttribute(hgemm<1>, cudaFuncAttributeMaxDynamicSharedMemorySize, SMEMB);
        cudaFuncSetAttribute(hgemm<2>, cudaFuncAttributeMaxDynamicSharedMemorySize, SMEMB);
        cudaFuncSetAttribute(hgemm<3>, cudaFuncAttributeMaxDynamicSharedMemorySize, SMEMB);
        cudaFuncSetAttribute(hgemm<4>, cudaFuncAttributeMaxDynamicSharedMemorySize, SMEMB);
        attr_set = 1;
    }

    zero_kernel<<<1, 32>>>();
    // weight conversions
    cvt_kernel<<<(DIMX*DIMX/8 + 255)/256, 256>>>(wq, p_wq16, DIMX*DIMX/8);
    cvt_kernel<<<(DIMX*KVD/8 + 255)/256, 256>>>(wk, p_wk16, DIMX*KVD/8);
    cvt_kernel<<<(DIMX*KVD/8 + 255)/256, 256>>>(wv, p_wv16, DIMX*KVD/8);
    cvt_kernel<<<(DIMX*DIMX/8 + 255)/256, 256>>>(wo, p_wo16, DIMX*DIMX/8);
    cvt_kernel<<<(NE*DIMX*FFX/8 + 255)/256, 256>>>(w1, p_w116, NE*DIMX*FFX/8);
    cvt_kernel<<<(NE*FFX*DIMX/8 + 255)/256, 256>>>(w2, p_w216, NE*FFX*DIMX/8);

    ln_kernel<<<TKN, 256>>>(x, ln1g, ln1b, p_h1h);

    hgemm<4><<<dim3((DIMX+2*KVD)/128, TKN/128, 1), 256, SMEMB>>>(
        p_h1h, nullptr, nullptr, nullptr, TKN, DIMX, DIMX);

    rope_kernel<<<(TKN*(NH+NKV)*32)/256, 256>>>();
    attn_f16_kernel<<<dim3(SEQ/128, NH, BATCH), 256, FSM_TOT>>>();

    hgemm<1><<<dim3(DIMX/128, TKN/128, 1), 256, SMEMB>>>(
        p_attnh, p_wo16, p_x1, x, TKN, DIMX, DIMX);
    ln_kernel<<<TKN, 256>>>(p_x1, ln2g, ln2b, p_h2h);

    router_kernel<<<TKN/8, 256>>>(wg);

    hgemm<2><<<dim3(FFX/128,  TKN/128, NE), 256, SMEMB>>>(
        nullptr, nullptr, nullptr, nullptr, TKN, FFX, DIMX);
    hgemm<3><<<dim3(DIMX/128, TKN/128, NE), 256, SMEMB>>>(
        nullptr, nullptr, nullptr, nullptr, TKN, DIMX, FFX);

    combine_kernel<<<(TKN*DIMX)/256, 256>>>(out);
    lb_kernel<<<1, 32>>>(out, out_size);
}

// round 12
// speedup vs baseline: 1.1201x; 1.0180x over previous
#include <cuda_runtime.h>
#include <cuda_fp16.h>
#include <math.h>

#define TKN 2048
#define BATCH 2
#define SEQ 1024
#define DIMX 1024
#define NH 16
#define NKV 4
#define HD 64
#define KVD (NKV*HD)   // 256
#define NE 8
#define FFX 4096

// ---------------- scratch ----------------
__device__ float g_x1[TKN*DIMX];
__device__ float g_part[2*TKN*DIMX];
__device__ __half g_qh [TKN*DIMX];
__device__ __half g_kh [TKN*KVD];
__device__ __half g_vh [TKN*KVD];
__device__ __half g_h1h [TKN*DIMX];
__device__ __half g_attnh[TKN*DIMX];
__device__ __half g_h2h [TKN*DIMX];
__device__ __half g_hidh[(size_t)NE*TKN*FFX];
__device__ __half g_wq16[DIMX*DIMX];
__device__ __half g_wk16[DIMX*KVD];
__device__ __half g_wv16[DIMX*KVD];
__device__ __half g_wo16[DIMX*DIMX];
__device__ __half g_w116[(size_t)NE*DIMX*FFX];
__device__ __half g_w216[(size_t)NE*FFX*DIMX];
__device__ int   g_tok [NE*TKN];
__device__ float g_gate[NE*TKN];
__device__ int   g_dest[NE*TKN];
__device__ int   g_ecnt[NE];
__device__ int   g_counts[NE];

// ---------------- merged fp32->fp16 convert (all weights) + counter zero ----------------
__device__ __forceinline__ void cvt8(const float* __restrict__ s, __half* __restrict__ d, int i) {
    float4 a = ((const float4*)s)[2*i];
    float4 b = ((const float4*)s)[2*i + 1];
    __half2 h0 = __floats2half2_rn(a.x, a.y);
    __half2 h1 = __floats2half2_rn(a.z, a.w);
    __half2 h2 = __floats2half2_rn(b.x, b.y);
    __half2 h3 = __floats2half2_rn(b.z, b.w);
    uint4 u;
    u.x = ((unsigned)__half_as_ushort(__high2half(h0)) << 16) | __half_as_ushort(__low2half(h0));
    u.y = ((unsigned)__half_as_ushort(__high2half(h1)) << 16) | __half_as_ushort(__low2half(h1));
    u.z = ((unsigned)__half_as_ushort(__high2half(h2)) << 16) | __half_as_ushort(__low2half(h2));
    u.w = ((unsigned)__half_as_ushort(__high2half(h3)) << 16) | __half_as_ushort(__low2half(h3));
    ((uint4*)d)[i] = u;
}

// chunk ranges (units of 8 floats)
#define RQ  131072
#define RK  (RQ + 32768)
#define RV  (RK + 32768)
#define RO  (RV + 131072)
#define R1  (RO + 4194304)
#define R2  (R1 + 4194304)   // 8716288 = 34048 * 256

__global__ void cvt_all_kernel(const float* __restrict__ wq, const float* __restrict__ wk,
                               const float* __restrict__ wv, const float* __restrict__ wo,
                               const float* __restrict__ w1, const float* __restrict__ w2) {
    int i = blockIdx.x*256 + threadIdx.x;
    if (blockIdx.x == 0 && threadIdx.x < NE) { g_ecnt[threadIdx.x] = 0; g_counts[threadIdx.x] = 0; }
    if (i < RQ)      cvt8(wq, g_wq16, i);
    else if (i < RK) cvt8(wk, g_wk16, i - RQ);
    else if (i < RV) cvt8(wv, g_wv16, i - RK);
    else if (i < RO) cvt8(wo, g_wo16, i - RV);
    else if (i < R1) cvt8(w1, g_w116, i - RO);
    else             cvt8(w2, g_w216, i - R1);
}

// ---------------- layernorm -> fp16 ----------------
__global__ void ln_kernel(const float* __restrict__ x, const float* __restrict__ g,
                          const float* __restrict__ b, __half* __restrict__ out) {
    int row = blockIdx.x;
    int tid = threadIdx.x;
    const float* xr = x + (size_t)row * DIMX;
    float v[4]; float s = 0.f;
    #pragma unroll
    for (int j = 0; j < 4; j++) { v[j] = xr[tid + 256*j]; s += v[j]; }
    __shared__ float red[8];
    #pragma unroll
    for (int o = 16; o > 0; o >>= 1) s += __shfl_xor_sync(0xffffffffu, s, o);
    if ((tid & 31) == 0) red[tid >> 5] = s;
    __syncthreads();
    float tot = red[0]+red[1]+red[2]+red[3]+red[4]+red[5]+red[6]+red[7];
    float mu = tot / DIMX;
    float sq = 0.f;
    #pragma unroll
    for (int j = 0; j < 4; j++) { float d = v[j]-mu; sq += d*d; }
    #pragma unroll
    for (int o = 16; o > 0; o >>= 1) sq += __shfl_xor_sync(0xffffffffu, sq, o);
    __syncthreads();
    if ((tid & 31) == 0) red[tid >> 5] = sq;
    __syncthreads();
    float vtot = red[0]+red[1]+red[2]+red[3]+red[4]+red[5]+red[6]+red[7];
    float rstd = rsqrtf(vtot / DIMX + 1e-5f);
    #pragma unroll
    for (int j = 0; j < 4; j++) {
        int d = tid + 256*j;
        out[(size_t)row*DIMX + d] = __float2half_rn((v[j]-mu)*rstd*g[d] + b[d]);
    }
}

// ---------------- shared mma macros ----------------
#define LDSM4(R, addr) \
    asm volatile("ldmatrix.sync.aligned.m8n8.x4.shared.b16 {%0,%1,%2,%3}, [%4];" \
        : "=r"(R[0]), "=r"(R[1]), "=r"(R[2]), "=r"(R[3]) : "r"(addr))
#define LDSM4T(R, addr) \
    asm volatile("ldmatrix.sync.aligned.m8n8.x4.trans.shared.b16 {%0,%1,%2,%3}, [%4];" \
        : "=r"(R[0]), "=r"(R[1]), "=r"(R[2]), "=r"(R[3]) : "r"(addr))
#define MMA_F16(C4, A4, B0, B1) \
    asm volatile("mma.sync.aligned.m16n8k16.row.col.f32.f16.f16.f32 " \
        "{%0,%1,%2,%3},{%4,%5,%6,%7},{%8,%9},{%0,%1,%2,%3};" \
        : "+f"(C4[0]), "+f"(C4[1]), "+f"(C4[2]), "+f"(C4[3]) \
        : "r"(A4[0]), "r"(A4[1]), "r"(A4[2]), "r"(A4[3]), "r"(B0), "r"(B1))

// ---------------- fp16 tensor-core GEMM (m16n8k16, ldmatrix, 3-stage) ----------------
// MODE 1: C=A@B+resid (fp32 out)  MODE 2: MoE up (gather, GELU, fp16 out)
// MODE 3: MoE down (scatter*gate, fp32)  MODE 4: fused QKV (fp16 q/k/v out)
// MoE modes: m-tile on blockIdx.x (fastest) so consecutive CTAs share one B slab (L2 reuse).
#define ASTG (128*40)
#define BSTG (32*136)
#define BBASE (3*ASTG)
#define SMEMB ((BBASE + 3*BSTG)*2)

template<int MODE>
__global__ __launch_bounds__(256, 2)
void hgemm(const __half* __restrict__ A, const __half* __restrict__ Bm,
           float* __restrict__ C, const float* __restrict__ resid,
           int M, int N, int K) {
    extern __shared__ __half smh[];
    int e = blockIdx.z;
    int ldB = N, ldC = N;
    int n0, m0;
    if (MODE == 2 || MODE == 3) { m0 = blockIdx.x * 128; n0 = blockIdx.y * 128; }
    else                        { n0 = blockIdx.x * 128; m0 = blockIdx.y * 128; }
    int cbase = n0;
    __half* C16 = nullptr;
    if (MODE == 2) { M = g_ecnt[e]; A = g_h2h; Bm = g_w116 + (size_t)e*DIMX*FFX; C16 = g_hidh + (size_t)e*TKN*FFX; }
    if (MODE == 3) { M = g_ecnt[e]; A = g_hidh + (size_t)e*TKN*FFX; Bm = g_w216 + (size_t)e*FFX*DIMX; ldC = DIMX; }
    if (MODE == 4) {
        if (n0 < DIMX)            { Bm = g_wq16; ldB = DIMX; C16 = g_qh; ldC = DIMX; cbase = n0; }
        else if (n0 < DIMX + KVD) { Bm = g_wk16; ldB = KVD;  C16 = g_kh; ldC = KVD;  cbase = n0 - DIMX; }
        else                      { Bm = g_wv16; ldB = KVD;  C16 = g_vh; ldC = KVD;  cbase = n0 - DIMX - KVD; }
    }
    if (m0 >= M) return;
    int tid = threadIdx.x;
    int warp = tid >> 5, lane = tid & 31;
    int wm = warp >> 2, wn = warp & 3;   // warp tile 64x32
    int g = lane >> 2, tg = lane & 3;

    const __half* aSrc[2]; int aSz[2]; unsigned aOff[2];
    #pragma unroll
    for (int p = 0; p < 2; p++) {
        int id = tid + p*256;
        int r = id >> 2, c8 = (id & 3) << 3;
        int rg = m0 + r;
        bool valid = rg < M;
        const __half* ptr;
        if (MODE == 2) {
            int t = valid ? g_tok[e*TKN + rg] : 0;
            ptr = A + (size_t)t*K + c8;
        } else {
            ptr = A + (size_t)(valid ? rg : 0)*K + c8;
        }
        aSrc[p] = ptr; aSz[p] = valid ? 16 : 0;
        aOff[p] = (r*40 + c8)*2;
    }
    const __half* bSrc[2]; unsigned bOff[2];
    #pragma unroll
    for (int p = 0; p < 2; p++) {
        int id = tid + p*256;
        int r = id >> 4, c8 = (id & 15) << 3;
        bSrc[p] = Bm + (size_t)r*ldB + cbase + c8;
        bOff[p] = (BBASE + r*136 + c8)*2;
    }
    unsigned smb = (unsigned)__cvta_generic_to_shared(smh);

    auto load_stage = [&](int s, int kt) {
        int k0 = kt*32;
        #pragma unroll
        for (int p = 0; p < 2; p++)
            asm volatile("cp.async.cg.shared.global [%0], [%1], 16, %2;"
                :: "r"(smb + s*(ASTG*2) + aOff[p]), "l"(aSrc[p] + k0), "r"(aSz[p]));
        #pragma unroll
        for (int p = 0; p < 2; p++)
            asm volatile("cp.async.cg.shared.global [%0], [%1], 16;"
                :: "r"(smb + s*(BSTG*2) + bOff[p]), "l"(bSrc[p] + (size_t)k0*ldB));
        asm volatile("cp.async.commit_group;");
    };

    unsigned aBase = smb + ((wm*64 + ((lane>>3)&1)*8 + (lane&7))*40 + (lane>>4)*8)*2;
    unsigned bBase = smb + BBASE*2 + ((((lane>>3)&1)*8 + (lane&7))*136 + wn*32 + (lane>>4)*8)*2;

    float c[4][4][4] = {};
    int nk = K / 32;
    load_stage(0, 0);
    load_stage(1, 1);
    for (int kt = 0; kt < nk; kt++) {
        int s = kt % 3;
        if (kt < nk - 1) asm volatile("cp.async.wait_group 1;");
        else             asm volatile("cp.async.wait_group 0;");
        __syncthreads();
        unsigned aS = aBase + s*(ASTG*2);
        unsigned bS = bBase + s*(BSTG*2);
        #pragma unroll
        for (int ks = 0; ks < 2; ks++) {
            unsigned af[4][4], bq[2][4];
            #pragma unroll
            for (int i = 0; i < 4; i++)
                LDSM4(af[i], aS + (i*16*40 + ks*16)*2);
            #pragma unroll
            for (int jp = 0; jp < 2; jp++)
                LDSM4T(bq[jp], bS + (ks*16*136 + jp*16)*2);
            #pragma unroll
            for (int i = 0; i < 4; i++)
                #pragma unroll
                for (int j = 0; j < 4; j++)
                    MMA_F16(c[i][j], af[i], bq[j>>1][(j&1)*2], bq[j>>1][(j&1)*2+1]);
        }
        if (kt + 2 < nk) load_stage((kt+2) % 3, kt+2);
    }

    #pragma unroll
    for (int i = 0; i < 4; i++) {
        #pragma unroll
        for (int half = 0; half < 2; half++) {
            int r = m0 + wm*64 + i*16 + g + half*8;
            if ((MODE == 2 || MODE == 3) && r >= M) continue;
            #pragma unroll
            for (int j = 0; j < 4; j++) {
                float v0 = c[i][j][half*2 + 0];
                float v1 = c[i][j][half*2 + 1];
                int col = cbase + wn*32 + j*8 + 2*tg;
                if (MODE == 4) {
                    *(__half2*)&C16[(size_t)r*ldC + col] = __floats2half2_rn(v0, v1);
                } else if (MODE == 1) {
                    float2 rr = *(const float2*)&resid[(size_t)r*ldC + col];
                    *(float2*)&C[(size_t)r*ldC + col] = make_float2(v0+rr.x, v1+rr.y);
                } else if (MODE == 2) {
                    float o0 = 0.5f*v0*(1.0f + erff(v0*0.70710678118654752f));
                    float o1 = 0.5f*v1*(1.0f + erff(v1*0.70710678118654752f));
                    *(__half2*)&C16[(size_t)r*ldC + col] = __floats2half2_rn(o0, o1);
                } else {
                    int p = g_dest[e*TKN + r];
                    float s = g_gate[e*TKN + r];
                    *(float2*)&g_part[(size_t)p*DIMX + col] = make_float2(s*v0, s*v1);
                }
            }
        }
    }
}

// ---------------- RoPE (fp16 in place) ----------------
__global__ void rope_kernel() {
    int idx = blockIdx.x*blockDim.x + threadIdx.x;
    const int totq = TKN*NH*32;
    const int totk = TKN*NKV*32;
    __half* arr; size_t base; int t, i;
    if (idx < totq) {
        arr = g_qh; i = idx & 31; int rest = idx >> 5;
        int head = rest % NH; t = rest / NH;
        base = (size_t)t*DIMX + head*HD;
    } else {
        idx -= totq;
        if (idx >= totk) return;
        arr = g_kh; i = idx & 31; int rest = idx >> 5;
        int head = rest % NKV; t = rest / NKV;
        base = (size_t)t*KVD + head*HD;
    }
    int pos = t % SEQ;
    float freq = expf(-(float)(2*i) * (9.210340371976184f / 64.0f));
    float ang = (float)pos * freq;
    float cs = cosf(ang), sn = sinf(ang);
    float x1 = __half2float(arr[base + i]), x2 = __half2float(arr[base + 32 + i]);
    arr[base + i]      = __float2half_rn(x1*cs - x2*sn);
    arr[base + 32 + i] = __float2half_rn(x2*cs + x1*sn);
}

// ---------------- fp16 tensor-core flash attention (shuffle-free P@V) ----------------
#define FSTR 72
#define FSM_Q 0
#define FSM_K (128*FSTR)
#define FSM_V (FSM_K + 2*64*FSTR)
#define FSM_TOT ((FSM_V + 2*64*FSTR)*2)

__global__ __launch_bounds__(256, 2)
void attn_f16_kernel() {
    extern __shared__ __half smA[];
    int bx = blockIdx.x, h = blockIdx.y, b = blockIdx.z;
    int hk = h >> 2;
    int q0 = bx * 128;
    int tid = threadIdx.x, w = tid >> 5, lane = tid & 31;
    int g = lane >> 2, tg = lane & 3;
    unsigned smb = (unsigned)__cvta_generic_to_shared(smA);
    int lrow = (lane & 7) + ((lane >> 3) & 1)*8;
    int lcol8 = (lane >> 4)*8;

    #pragma unroll
    for (int p = 0; p < 4; p++) {
        int id = tid + p*256;
        int r = id >> 3, c8 = (id & 7) << 3;
        asm volatile("cp.async.cg.shared.global [%0], [%1], 16;"
            :: "r"(smb + (FSM_Q + r*FSTR + c8)*2),
               "l"(g_qh + (size_t)(b*SEQ + q0 + r)*DIMX + h*HD + c8));
    }
    auto load_kv = [&](int kt, int bf) {
        #pragma unroll
        for (int p = 0; p < 2; p++) {
            int id = tid + p*256;
            int r = id >> 3, c8 = (id & 7) << 3;
            asm volatile("cp.async.cg.shared.global [%0], [%1], 16;"
                :: "r"(smb + (FSM_K + bf*64*FSTR + r*FSTR + c8)*2),
                   "l"(g_kh + (size_t)(b*SEQ + kt*64 + r)*KVD + hk*HD + c8));
            asm volatile("cp.async.cg.shared.global [%0], [%1], 16;"
                :: "r"(smb + (FSM_V + bf*64*FSTR + r*FSTR + c8)*2),
                   "l"(g_vh + (size_t)(b*SEQ + kt*64 + r)*KVD + hk*HD + c8));
        }
    };
    int nkt = 2*bx + 2;
    load_kv(0, 0);
    asm volatile("cp.async.commit_group;");

    int my_last = 2*bx + (w >= 4 ? 1 : 0);
    float m0 = -1.0e30f, m1 = -1.0e30f, l0 = 0.f, l1 = 0.f;
    float o[8][4] = {};
    const float SCALE = 0.18033688011112042f;

    unsigned qBase = smb + ((FSM_Q + (16*w + lrow)*FSTR) + lcol8)*2;

    for (int kt = 0; kt < nkt; kt++) {
        int bf = kt & 1;
        if (kt + 1 < nkt) {
            load_kv(kt + 1, bf ^ 1);
            asm volatile("cp.async.commit_group;");
            asm volatile("cp.async.wait_group 1;");
        } else {
            asm volatile("cp.async.wait_group 0;");
        }
        __syncthreads();

        if (kt <= my_last) {
            unsigned kBase = smb + ((FSM_K + bf*64*FSTR + lrow*FSTR) + lcol8)*2;
            unsigned vBase = smb + ((FSM_V + bf*64*FSTR + lrow*FSTR) + lcol8)*2;

            float s[8][4] = {};
            #pragma unroll
            for (int ks = 0; ks < 4; ks++) {
                unsigned af[4], kb[4][4];
                LDSM4(af, qBase + ks*32);
                #pragma unroll
                for (int j2 = 0; j2 < 4; j2++)
                    LDSM4(kb[j2], kBase + (j2*16*FSTR)*2 + ks*32);
                #pragma unroll
                for (int j = 0; j < 8; j++)
                    MMA_F16(s[j], af, kb[j>>1][j&1], kb[j>>1][(j&1)+2]);
            }
            if (kt == my_last) {
                int r0 = q0 + 16*w + g, r1 = r0 + 8;
                #pragma unroll
                for (int j = 0; j < 8; j++) {
                    int cg = kt*64 + j*8 + 2*tg;
                    s[j][0] = (cg   > r0) ? -1.0e30f : s[j][0]*SCALE;
                    s[j][1] = (cg+1 > r0) ? -1.0e30f : s[j][1]*SCALE;
                    s[j][2] = (cg   > r1) ? -1.0e30f : s[j][2]*SCALE;
                    s[j][3] = (cg+1 > r1) ? -1.0e30f : s[j][3]*SCALE;
                }
            } else {
                #pragma unroll
                for (int j = 0; j < 8; j++)
                    #pragma unroll
                    for (int q = 0; q < 4; q++) s[j][q] *= SCALE;
            }
            float mx0 = -1.0e30f, mx1 = -1.0e30f;
            #pragma unroll
            for (int j = 0; j < 8; j++) {
                mx0 = fmaxf(mx0, fmaxf(s[j][0], s[j][1]));
                mx1 = fmaxf(mx1, fmaxf(s[j][2], s[j][3]));
            }
            mx0 = fmaxf(mx0, __shfl_xor_sync(0xffffffffu, mx0, 1));
            mx0 = fmaxf(mx0, __shfl_xor_sync(0xffffffffu, mx0, 2));
            mx1 = fmaxf(mx1, __shfl_xor_sync(0xffffffffu, mx1, 1));
            mx1 = fmaxf(mx1, __shfl_xor_sync(0xffffffffu, mx1, 2));
            float mn0 = fmaxf(m0, mx0), mn1 = fmaxf(m1, mx1);
            float c0 = exp2f(m0 - mn0), c1 = exp2f(m1 - mn1);
            float rs0 = 0.f, rs1 = 0.f;
            #pragma unroll
            for (int j = 0; j < 8; j++) {
                s[j][0] = exp2f(s[j][0] - mn0); s[j][1] = exp2f(s[j][1] - mn0);
                s[j][2] = exp2f(s[j][2] - mn1); s[j][3] = exp2f(s[j][3] - mn1);
                rs0 += s[j][0] + s[j][1];
                rs1 += s[j][2] + s[j][3];
            }
            rs0 += __shfl_xor_sync(0xffffffffu, rs0, 1);
            rs0 += __shfl_xor_sync(0xffffffffu, rs0, 2);
            rs1 += __shfl_xor_sync(0xffffffffu, rs1, 1);
            rs1 += __shfl_xor_sync(0xffffffffu, rs1, 2);
            l0 = l0*c0 + rs0; l1 = l1*c1 + rs1;
            m0 = mn0; m1 = mn1;
            #pragma unroll
            for (int j = 0; j < 8; j++) {
                o[j][0] *= c0; o[j][1] *= c0;
                o[j][2] *= c1; o[j][3] *= c1;
            }
            #pragma unroll
            for (int kk = 0; kk < 4; kk++) {
                __half2 p0 = __floats2half2_rn(s[2*kk  ][0], s[2*kk  ][1]);
                __half2 p1 = __floats2half2_rn(s[2*kk  ][2], s[2*kk  ][3]);
                __half2 p2 = __floats2half2_rn(s[2*kk+1][0], s[2*kk+1][1]);
                __half2 p3 = __floats2half2_rn(s[2*kk+1][2], s[2*kk+1][3]);
                unsigned pa[4] = { *(unsigned*)&p0, *(unsigned*)&p1,
                                   *(unsigned*)&p2, *(unsigned*)&p3 };
                #pragma unroll
                for (int j2 = 0; j2 < 4; j2++) {
                    unsigned vb[4];
                    LDSM4T(vb, vBase + (kk*16*FSTR + j2*16)*2);
                    MMA_F16(o[2*j2  ], pa, vb[0], vb[1]);
                    MMA_F16(o[2*j2+1], pa, vb[2], vb[3]);
                }
            }
        }
        __syncthreads();
    }

    float i0 = 1.0f / l0, i1 = 1.0f / l1;
    size_t r0b = (size_t)(b*SEQ + q0 + 16*w + g    )*DIMX + h*HD;
    size_t r1b = (size_t)(b*SEQ + q0 + 16*w + g + 8)*DIMX + h*HD;
    #pragma unroll
    for (int j = 0; j < 8; j++) {
        int col = j*8 + 2*tg;
        *(__half2*)&g_attnh[r0b + col] = __floats2half2_rn(o[j][0]*i0, o[j][1]*i0);
        *(__half2*)&g_attnh[r1b + col] = __floats2half2_rn(o[j][2]*i1, o[j][3]*i1);
    }
}

// ---------------- router ----------------
__global__ void router_kernel(const float* __restrict__ wg) {
    int warp = (blockIdx.x*blockDim.x + threadIdx.x) >> 5;
    int lane = threadIdx.x & 31;
    if (warp >= TKN) return;
    int t = warp;
    float acc[NE] = {};
    const __half* hr = g_h2h + (size_t)t*DIMX;
    for (int d = lane; d < DIMX; d += 32) {
        float hv = __half2float(hr[d]);
        const float* wr = wg + (size_t)d*NE;
        #pragma unroll
        for (int e = 0; e < NE; e++) acc[e] += hv * wr[e];
    }
    #pragma unroll
    for (int e = 0; e < NE; e++)
        #pragma unroll
        for (int off = 16; off > 0; off >>= 1)
            acc[e] += __shfl_xor_sync(0xffffffffu, acc[e], off);
    if (lane == 0) {
        int e0 = 0; float v0 = acc[0];
        #pragma unroll
        for (int e = 1; e < NE; e++) if (acc[e] > v0) { v0 = acc[e]; e0 = e; }
        int e1 = -1; float v1 = -3.4e38f;
        #pragma unroll
        for (int e = 0; e < NE; e++) if (e != e0 && acc[e] > v1) { v1 = acc[e]; e1 = e; }
        float ex = expf(v1 - v0);
        float den = 1.0f + ex;
        float gg0 = 1.0f/den, gg1 = ex/den;
        atomicAdd(&g_counts[e0], 1); atomicAdd(&g_counts[e1], 1);
        int p0 = atomicAdd(&g_ecnt[e0], 1);
        g_tok[e0*TKN+p0] = t; g_gate[e0*TKN+p0] = gg0; g_dest[e0*TKN+p0] = t;
        int p1 = atomicAdd(&g_ecnt[e1], 1);
        g_tok[e1*TKN+p1] = t; g_gate[e1*TKN+p1] = gg1; g_dest[e1*TKN+p1] = TKN + t;
    }
}

__global__ void combine_kernel(float* __restrict__ out) {
    int i = blockIdx.x*256 + threadIdx.x;
    out[i] = g_x1[i] + g_part[i] + g_part[TKN*DIMX + i];
}

__global__ void lb_kernel(float* __restrict__ out, int out_size) {
    if (threadIdx.x == 0) {
        float tot = 0.f;
        for (int e = 0; e < NE; e++) tot += (float)g_counts[e];
        float loss = 0.f;
        for (int e = 0; e < NE; e++) {
            float cn = (float)g_counts[e]/tot - 1.0f/NE;
            loss += cn*cn;
        }
        out[out_size - 1] = loss / NE;
    }
}

// ---------------- launch ----------------
extern "C" void kernel_launch(void* const* d_in, const int* in_sizes, int n_in,
                              void* d_out, int out_size) {
    const float* x    = (const float*)d_in[0];
    const float* wq   = (const float*)d_in[1];
    const float* wk   = (const float*)d_in[2];
    const float* wv   = (const float*)d_in[3];
    const float* wo   = (const float*)d_in[4];
    const float* wg   = (const float*)d_in[5];
    const float* w1   = (const float*)d_in[6];
    const float* w2   = (const float*)d_in[7];
    const float* ln1g = (const float*)d_in[8];
    const float* ln1b = (const float*)d_in[9];
    const float* ln2g = (const float*)d_in[10];
    const float* ln2b = (const float*)d_in[11];
    float* out = (float*)d_out;

    float *p_x1;
    __half *p_h1h, *p_attnh, *p_h2h, *p_wo16;
    cudaGetSymbolAddress((void**)&p_x1,   g_x1);
    cudaGetSymbolAddress((void**)&p_h1h,  g_h1h);
    cudaGetSymbolAddress((void**)&p_attnh,g_attnh);
    cudaGetSymbolAddress((void**)&p_h2h,  g_h2h);
    cudaGetSymbolAddress((void**)&p_wo16, g_wo16);

    static int attr_set = 0;
    if (!attr_set) {
        cudaFuncSetAttribute(attn_f16_kernel,
                             cudaFuncAttributeMaxDynamicSharedMemorySize, FSM_TOT);
        cudaFuncSetAttribute(hgemm<1>, cudaFuncAttributeMaxDynamicSharedMemorySize, SMEMB);
        cudaFuncSetAttribute(hgemm<2>, cudaFuncAttributeMaxDynamicSharedMemorySize, SMEMB);
        cudaFuncSetAttribute(hgemm<3>, cudaFuncAttributeMaxDynamicSharedMemorySize, SMEMB);
        cudaFuncSetAttribute(hgemm<4>, cudaFuncAttributeMaxDynamicSharedMemorySize, SMEMB);
        attr_set = 1;
    }

    // all weight conversions + counter zeroing, single launch
    cvt_all_kernel<<<R2/256, 256>>>(wq, wk, wv, wo, w1, w2);

    ln_kernel<<<TKN, 256>>>(x, ln1g, ln1b, p_h1h);

    hgemm<4><<<dim3((DIMX+2*KVD)/128, TKN/128, 1), 256, SMEMB>>>(
        p_h1h, nullptr, nullptr, nullptr, TKN, DIMX, DIMX);

    rope_kernel<<<(TKN*(NH+NKV)*32)/256, 256>>>();
    attn_f16_kernel<<<dim3(SEQ/128, NH, BATCH), 256, FSM_TOT>>>();

    hgemm<1><<<dim3(DIMX/128, TKN/128, 1), 256, SMEMB>>>(
        p_attnh, p_wo16, p_x1, x, TKN, DIMX, DIMX);
    ln_kernel<<<TKN, 256>>>(p_x1, ln2g, ln2b, p_h2h);

    router_kernel<<<TKN/8, 256>>>(wg);

    // MoE: m-tiles on x (fastest) -> consecutive CTAs share B slab
    hgemm<2><<<dim3(TKN/128, FFX/128,  NE), 256, SMEMB>>>(
        nullptr, nullptr, nullptr, nullptr, TKN, FFX, DIMX);
    hgemm<3><<<dim3(TKN/128, DIMX/128, NE), 256, SMEMB>>>(
        nullptr, nullptr, nullptr, nullptr, TKN, DIMX, FFX);

    combine_kernel<<<(TKN*DIMX)/256, 256>>>(out);
    lb_kernel<<<1, 32>>>(out, out_size);
}

// round 15
// speedup vs baseline: 1.1511x; 1.0276x over previous
#include <cuda_runtime.h>
#include <cuda_fp16.h>
#include <math.h>

#define TKN 2048
#define BATCH 2
#define SEQ 1024
#define DIMX 1024
#define NH 16
#define NKV 4
#define HD 64
#define KVD (NKV*HD)   // 256
#define NE 8
#define FFX 4096

// ---------------- scratch ----------------
__device__ float g_x1[TKN*DIMX];
__device__ float g_part[2*TKN*DIMX];
__device__ __half g_qh [TKN*DIMX];
__device__ __half g_kh [TKN*KVD];
__device__ __half g_vh [TKN*KVD];
__device__ __half g_h1h [TKN*DIMX];
__device__ __half g_attnh[TKN*DIMX];
__device__ __half g_h2h [TKN*DIMX];
__device__ __half g_hidh[(size_t)NE*TKN*FFX];
__device__ __half g_wq16[DIMX*DIMX];
__device__ __half g_wk16[DIMX*KVD];
__device__ __half g_wv16[DIMX*KVD];
__device__ __half g_wo16[DIMX*DIMX];
__device__ __half g_w116[(size_t)NE*DIMX*FFX];
__device__ __half g_w216[(size_t)NE*FFX*DIMX];
__device__ int   g_tok [NE*TKN];
__device__ float g_gate[NE*TKN];
__device__ int   g_dest[NE*TKN];
__device__ int   g_ecnt[NE];
__device__ int   g_counts[NE];

// ---------------- fp32 -> fp16 helpers ----------------
__device__ __forceinline__ void cvt8(const float* __restrict__ s, __half* __restrict__ d, int i) {
    float4 a = ((const float4*)s)[2*i];
    float4 b = ((const float4*)s)[2*i + 1];
    __half2 h0 = __floats2half2_rn(a.x, a.y);
    __half2 h1 = __floats2half2_rn(a.z, a.w);
    __half2 h2 = __floats2half2_rn(b.x, b.y);
    __half2 h3 = __floats2half2_rn(b.z, b.w);
    uint4 u;
    u.x = ((unsigned)__half_as_ushort(__high2half(h0)) << 16) | __half_as_ushort(__low2half(h0));
    u.y = ((unsigned)__half_as_ushort(__high2half(h1)) << 16) | __half_as_ushort(__low2half(h1));
    u.z = ((unsigned)__half_as_ushort(__high2half(h2)) << 16) | __half_as_ushort(__low2half(h2));
    u.w = ((unsigned)__half_as_ushort(__high2half(h3)) << 16) | __half_as_ushort(__low2half(h3));
    ((uint4*)d)[i] = u;
}

// dense weights (+ counter zero): ranges in 8-float units
#define DQ 131072
#define DK (DQ + 32768)
#define DV (DK + 32768)
#define DO (DV + 131072)     // 327680 = 1280 * 256
__global__ void cvt_dense_kernel(const float* __restrict__ wq, const float* __restrict__ wk,
                                 const float* __restrict__ wv, const float* __restrict__ wo) {
    int i = blockIdx.x*256 + threadIdx.x;
    if (blockIdx.x == 0 && threadIdx.x < NE) { g_ecnt[threadIdx.x] = 0; g_counts[threadIdx.x] = 0; }
    if (i < DQ)      cvt8(wq, g_wq16, i);
    else if (i < DK) cvt8(wk, g_wk16, i - DQ);
    else if (i < DV) cvt8(wv, g_wv16, i - DK);
    else             cvt8(wo, g_wo16, i - DV);
}

// ---------------- layernorm -> fp16 ----------------
__global__ void ln_kernel(const float* __restrict__ x, const float* __restrict__ g,
                          const float* __restrict__ b, __half* __restrict__ out) {
    int row = blockIdx.x;
    int tid = threadIdx.x;
    const float* xr = x + (size_t)row * DIMX;
    float v[4]; float s = 0.f;
    #pragma unroll
    for (int j = 0; j < 4; j++) { v[j] = xr[tid + 256*j]; s += v[j]; }
    __shared__ float red[8];
    #pragma unroll
    for (int o = 16; o > 0; o >>= 1) s += __shfl_xor_sync(0xffffffffu, s, o);
    if ((tid & 31) == 0) red[tid >> 5] = s;
    __syncthreads();
    float tot = red[0]+red[1]+red[2]+red[3]+red[4]+red[5]+red[6]+red[7];
    float mu = tot / DIMX;
    float sq = 0.f;
    #pragma unroll
    for (int j = 0; j < 4; j++) { float d = v[j]-mu; sq += d*d; }
    #pragma unroll
    for (int o = 16; o > 0; o >>= 1) sq += __shfl_xor_sync(0xffffffffu, sq, o);
    __syncthreads();
    if ((tid & 31) == 0) red[tid >> 5] = sq;
    __syncthreads();
    float vtot = red[0]+red[1]+red[2]+red[3]+red[4]+red[5]+red[6]+red[7];
    float rstd = rsqrtf(vtot / DIMX + 1e-5f);
    #pragma unroll
    for (int j = 0; j < 4; j++) {
        int d = tid + 256*j;
        out[(size_t)row*DIMX + d] = __float2half_rn((v[j]-mu)*rstd*g[d] + b[d]);
    }
}

// ---------------- shared mma macros ----------------
#define LDSM4(R, addr) \
    asm volatile("ldmatrix.sync.aligned.m8n8.x4.shared.b16 {%0,%1,%2,%3}, [%4];" \
        : "=r"(R[0]), "=r"(R[1]), "=r"(R[2]), "=r"(R[3]) : "r"(addr))
#define LDSM4T(R, addr) \
    asm volatile("ldmatrix.sync.aligned.m8n8.x4.trans.shared.b16 {%0,%1,%2,%3}, [%4];" \
        : "=r"(R[0]), "=r"(R[1]), "=r"(R[2]), "=r"(R[3]) : "r"(addr))
#define MMA_F16(C4, A4, B0, B1) \
    asm volatile("mma.sync.aligned.m16n8k16.row.col.f32.f16.f16.f32 " \
        "{%0,%1,%2,%3},{%4,%5,%6,%7},{%8,%9},{%0,%1,%2,%3};" \
        : "+f"(C4[0]), "+f"(C4[1]), "+f"(C4[2]), "+f"(C4[3]) \
        : "r"(A4[0]), "r"(A4[1]), "r"(A4[2]), "r"(A4[3]), "r"(B0), "r"(B1))

#define ASTG (128*40)
#define BSTG (32*136)
#define BBASE (3*ASTG)
#define SMEMB ((BBASE + 3*BSTG)*2)

// ---------------- fp16 tensor-core GEMM (m16n8k16, ldmatrix, 3-stage) ----------------
// MODE 1: C=A@B+resid (fp32 out)  MODE 2: MoE up (gather, GELU, fp16 out)
// MODE 3: MoE down (scatter*gate, fp32)
// MoE modes: m-tile on blockIdx.x (fastest) so consecutive CTAs share one B slab.
template<int MODE>
__global__ __launch_bounds__(256, 2)
void hgemm(const __half* __restrict__ A, const __half* __restrict__ Bm,
           float* __restrict__ C, const float* __restrict__ resid,
           int M, int N, int K) {
    extern __shared__ __half smh[];
    int e = blockIdx.z;
    int ldB = N, ldC = N;
    int n0, m0;
    if (MODE == 2 || MODE == 3) { m0 = blockIdx.x * 128; n0 = blockIdx.y * 128; }
    else                        { n0 = blockIdx.x * 128; m0 = blockIdx.y * 128; }
    int cbase = n0;
    __half* C16 = nullptr;
    if (MODE == 2) { M = g_ecnt[e]; A = g_h2h; Bm = g_w116 + (size_t)e*DIMX*FFX; C16 = g_hidh + (size_t)e*TKN*FFX; }
    if (MODE == 3) { M = g_ecnt[e]; A = g_hidh + (size_t)e*TKN*FFX; Bm = g_w216 + (size_t)e*FFX*DIMX; ldC = DIMX; }
    if (m0 >= M) return;
    int tid = threadIdx.x;
    int warp = tid >> 5, lane = tid & 31;
    int wm = warp >> 2, wn = warp & 3;
    int g = lane >> 2, tg = lane & 3;

    const __half* aSrc[2]; int aSz[2]; unsigned aOff[2];
    #pragma unroll
    for (int p = 0; p < 2; p++) {
        int id = tid + p*256;
        int r = id >> 2, c8 = (id & 3) << 3;
        int rg = m0 + r;
        bool valid = rg < M;
        const __half* ptr;
        if (MODE == 2) {
            int t = valid ? g_tok[e*TKN + rg] : 0;
            ptr = A + (size_t)t*K + c8;
        } else {
            ptr = A + (size_t)(valid ? rg : 0)*K + c8;
        }
        aSrc[p] = ptr; aSz[p] = valid ? 16 : 0;
        aOff[p] = (r*40 + c8)*2;
    }
    const __half* bSrc[2]; unsigned bOff[2];
    #pragma unroll
    for (int p = 0; p < 2; p++) {
        int id = tid + p*256;
        int r = id >> 4, c8 = (id & 15) << 3;
        bSrc[p] = Bm + (size_t)r*ldB + cbase + c8;
        bOff[p] = (BBASE + r*136 + c8)*2;
    }
    unsigned smb = (unsigned)__cvta_generic_to_shared(smh);

    auto load_stage = [&](int s, int kt) {
        int k0 = kt*32;
        #pragma unroll
        for (int p = 0; p < 2; p++)
            asm volatile("cp.async.cg.shared.global [%0], [%1], 16, %2;"
                :: "r"(smb + s*(ASTG*2) + aOff[p]), "l"(aSrc[p] + k0), "r"(aSz[p]));
        #pragma unroll
        for (int p = 0; p < 2; p++)
            asm volatile("cp.async.cg.shared.global [%0], [%1], 16;"
                :: "r"(smb + s*(BSTG*2) + bOff[p]), "l"(bSrc[p] + (size_t)k0*ldB));
        asm volatile("cp.async.commit_group;");
    };

    unsigned aBase = smb + ((wm*64 + ((lane>>3)&1)*8 + (lane&7))*40 + (lane>>4)*8)*2;
    unsigned bBase = smb + BBASE*2 + ((((lane>>3)&1)*8 + (lane&7))*136 + wn*32 + (lane>>4)*8)*2;

    float c[4][4][4] = {};
    int nk = K / 32;
    load_stage(0, 0);
    load_stage(1, 1);
    for (int kt = 0; kt < nk; kt++) {
        int s = kt % 3;
        if (kt < nk - 1) asm volatile("cp.async.wait_group 1;");
        else             asm volatile("cp.async.wait_group 0;");
        __syncthreads();
        unsigned aS = aBase + s*(ASTG*2);
        unsigned bS = bBase + s*(BSTG*2);
        #pragma unroll
        for (int ks = 0; ks < 2; ks++) {
            unsigned af[4][4], bq[2][4];
            #pragma unroll
            for (int i = 0; i < 4; i++)
                LDSM4(af[i], aS + (i*16*40 + ks*16)*2);
            #pragma unroll
            for (int jp = 0; jp < 2; jp++)
                LDSM4T(bq[jp], bS + (ks*16*136 + jp*16)*2);
            #pragma unroll
            for (int i = 0; i < 4; i++)
                #pragma unroll
                for (int j = 0; j < 4; j++)
                    MMA_F16(c[i][j], af[i], bq[j>>1][(j&1)*2], bq[j>>1][(j&1)*2+1]);
        }
        if (kt + 2 < nk) load_stage((kt+2) % 3, kt+2);
    }

    #pragma unroll
    for (int i = 0; i < 4; i++) {
        #pragma unroll
        for (int half = 0; half < 2; half++) {
            int r = m0 + wm*64 + i*16 + g + half*8;
            if ((MODE == 2 || MODE == 3) && r >= M) continue;
            #pragma unroll
            for (int j = 0; j < 4; j++) {
                float v0 = c[i][j][half*2 + 0];
                float v1 = c[i][j][half*2 + 1];
                int col = cbase + wn*32 + j*8 + 2*tg;
                if (MODE == 1) {
                    float2 rr = *(const float2*)&resid[(size_t)r*ldC + col];
                    *(float2*)&C[(size_t)r*ldC + col] = make_float2(v0+rr.x, v1+rr.y);
                } else if (MODE == 2) {
                    float o0 = 0.5f*v0*(1.0f + erff(v0*0.70710678118654752f));
                    float o1 = 0.5f*v1*(1.0f + erff(v1*0.70710678118654752f));
                    *(__half2*)&C16[(size_t)r*ldC + col] = __floats2half2_rn(o0, o1);
                } else {
                    int p = g_dest[e*TKN + r];
                    float s = g_gate[e*TKN + r];
                    *(float2*)&g_part[(size_t)p*DIMX + col] = make_float2(s*v0, s*v1);
                }
            }
        }
    }
}

// ---------------- fused QKV GEMM + w1/w2 convert (single launch overlap) ----------------
// blocks [0,192): QKV GEMM (fp16 out). blocks [192, 192+4096): cvt w1/w2 -> fp16.
#define QKV_BLKS 192
#define CVT_UNITS_W (NE*DIMX*FFX/8)          // 4194304 per weight
#define CVT_BLKS 4096                        // 2*CVT_UNITS_W / (256*8)

__global__ __launch_bounds__(256, 2)
void qkv_cvt_kernel(const __half* __restrict__ A,
                    const float* __restrict__ w1, const float* __restrict__ w2) {
    if (blockIdx.x >= QKV_BLKS) {
        int b2 = blockIdx.x - QKV_BLKS;
        #pragma unroll
        for (int p = 0; p < 8; p++) {
            int u = b2*2048 + p*256 + threadIdx.x;
            if (u < CVT_UNITS_W) cvt8(w1, g_w116, u);
            else                 cvt8(w2, g_w216, u - CVT_UNITS_W);
        }
        return;
    }
    extern __shared__ __half smh[];
    int gid = blockIdx.x;
    int n0 = (gid % 12) * 128;
    int m0 = (gid / 12) * 128;
    const __half* Bm; __half* C16; int ldB, ldC, cbase;
    if (n0 < DIMX)            { Bm = g_wq16; ldB = DIMX; C16 = g_qh; ldC = DIMX; cbase = n0; }
    else if (n0 < DIMX + KVD) { Bm = g_wk16; ldB = KVD;  C16 = g_kh; ldC = KVD;  cbase = n0 - DIMX; }
    else                      { Bm = g_wv16; ldB = KVD;  C16 = g_vh; ldC = KVD;  cbase = n0 - DIMX - KVD; }
    const int K = DIMX;
    int tid = threadIdx.x;
    int warp = tid >> 5, lane = tid & 31;
    int wm = warp >> 2, wn = warp & 3;
    int g = lane >> 2, tg = lane & 3;

    const __half* aSrc[2]; unsigned aOff[2];
    #pragma unroll
    for (int p = 0; p < 2; p++) {
        int id = tid + p*256;
        int r = id >> 2, c8 = (id & 3) << 3;
        aSrc[p] = A + (size_t)(m0 + r)*K + c8;
        aOff[p] = (r*40 + c8)*2;
    }
    const __half* bSrc[2]; unsigned bOff[2];
    #pragma unroll
    for (int p = 0; p < 2; p++) {
        int id = tid + p*256;
        int r = id >> 4, c8 = (id & 15) << 3;
        bSrc[p] = Bm + (size_t)r*ldB + cbase + c8;
        bOff[p] = (BBASE + r*136 + c8)*2;
    }
    unsigned smb = (unsigned)__cvta_generic_to_shared(smh);

    auto load_stage = [&](int s, int kt) {
        int k0 = kt*32;
        #pragma unroll
        for (int p = 0; p < 2; p++)
            asm volatile("cp.async.cg.shared.global [%0], [%1], 16;"
                :: "r"(smb + s*(ASTG*2) + aOff[p]), "l"(aSrc[p] + k0));
        #pragma unroll
        for (int p = 0; p < 2; p++)
            asm volatile("cp.async.cg.shared.global [%0], [%1], 16;"
                :: "r"(smb + s*(BSTG*2) + bOff[p]), "l"(bSrc[p] + (size_t)k0*ldB));
        asm volatile("cp.async.commit_group;");
    };

    unsigned aBase = smb + ((wm*64 + ((lane>>3)&1)*8 + (lane&7))*40 + (lane>>4)*8)*2;
    unsigned bBase = smb + BBASE*2 + ((((lane>>3)&1)*8 + (lane&7))*136 + wn*32 + (lane>>4)*8)*2;

    float c[4][4][4] = {};
    int nk = K / 32;
    load_stage(0, 0);
    load_stage(1, 1);
    for (int kt = 0; kt < nk; kt++) {
        int s = kt % 3;
        if (kt < nk - 1) asm volatile("cp.async.wait_group 1;");
        else             asm volatile("cp.async.wait_group 0;");
        __syncthreads();
        unsigned aS = aBase + s*(ASTG*2);
        unsigned bS = bBase + s*(BSTG*2);
        #pragma unroll
        for (int ks = 0; ks < 2; ks++) {
            unsigned af[4][4], bq[2][4];
            #pragma unroll
            for (int i = 0; i < 4; i++)
                LDSM4(af[i], aS + (i*16*40 + ks*16)*2);
            #pragma unroll
            for (int jp = 0; jp < 2; jp++)
                LDSM4T(bq[jp], bS + (ks*16*136 + jp*16)*2);
            #pragma unroll
            for (int i = 0; i < 4; i++)
                #pragma unroll
                for (int j = 0; j < 4; j++)
                    MMA_F16(c[i][j], af[i], bq[j>>1][(j&1)*2], bq[j>>1][(j&1)*2+1]);
        }
        if (kt + 2 < nk) load_stage((kt+2) % 3, kt+2);
    }

    #pragma unroll
    for (int i = 0; i < 4; i++) {
        #pragma unroll
        for (int half = 0; half < 2; half++) {
            int r = m0 + wm*64 + i*16 + g + half*8;
            #pragma unroll
            for (int j = 0; j < 4; j++) {
                int col = cbase + wn*32 + j*8 + 2*tg;
                *(__half2*)&C16[(size_t)r*ldC + col] =
                    __floats2half2_rn(c[i][j][half*2 + 0], c[i][j][half*2 + 1]);
            }
        }
    }
}

// ---------------- RoPE (fp16 in place) ----------------
__global__ void rope_kernel() {
    int idx = blockIdx.x*blockDim.x + threadIdx.x;
    const int totq = TKN*NH*32;
    const int totk = TKN*NKV*32;
    __half* arr; size_t base; int t, i;
    if (idx < totq) {
        arr = g_qh; i = idx & 31; int rest = idx >> 5;
        int head = rest % NH; t = rest / NH;
        base = (size_t)t*DIMX + head*HD;
    } else {
        idx -= totq;
        if (idx >= totk) return;
        arr = g_kh; i = idx & 31; int rest = idx >> 5;
        int head = rest % NKV; t = rest / NKV;
        base = (size_t)t*KVD + head*HD;
    }
    int pos = t % SEQ;
    float freq = expf(-(float)(2*i) * (9.210340371976184f / 64.0f));
    float ang = (float)pos * freq;
    float cs = cosf(ang), sn = sinf(ang);
    float x1 = __half2float(arr[base + i]), x2 = __half2float(arr[base + 32 + i]);
    arr[base + i]      = __float2half_rn(x1*cs - x2*sn);
    arr[base + 32 + i] = __float2half_rn(x2*cs + x1*sn);
}

// ---------------- fp16 tensor-core flash attention (shuffle-free P@V) ----------------
#define FSTR 72
#define FSM_Q 0
#define FSM_K (128*FSTR)
#define FSM_V (FSM_K + 2*64*FSTR)
#define FSM_TOT ((FSM_V + 2*64*FSTR)*2)

__global__ __launch_bounds__(256, 2)
void attn_f16_kernel() {
    extern __shared__ __half smA[];
    int bx = blockIdx.x, h = blockIdx.y, b = blockIdx.z;
    int hk = h >> 2;
    int q0 = bx * 128;
    int tid = threadIdx.x, w = tid >> 5, lane = tid & 31;
    int g = lane >> 2, tg = lane & 3;
    unsigned smb = (unsigned)__cvta_generic_to_shared(smA);
    int lrow = (lane & 7) + ((lane >> 3) & 1)*8;
    int lcol8 = (lane >> 4)*8;

    #pragma unroll
    for (int p = 0; p < 4; p++) {
        int id = tid + p*256;
        int r = id >> 3, c8 = (id & 7) << 3;
        asm volatile("cp.async.cg.shared.global [%0], [%1], 16;"
            :: "r"(smb + (FSM_Q + r*FSTR + c8)*2),
               "l"(g_qh + (size_t)(b*SEQ + q0 + r)*DIMX + h*HD + c8));
    }
    auto load_kv = [&](int kt, int bf) {
        #pragma unroll
        for (int p = 0; p < 2; p++) {
            int id = tid + p*256;
            int r = id >> 3, c8 = (id & 7) << 3;
            asm volatile("cp.async.cg.shared.global [%0], [%1], 16;"
                :: "r"(smb + (FSM_K + bf*64*FSTR + r*FSTR + c8)*2),
                   "l"(g_kh + (size_t)(b*SEQ + kt*64 + r)*KVD + hk*HD + c8));
            asm volatile("cp.async.cg.shared.global [%0], [%1], 16;"
                :: "r"(smb + (FSM_V + bf*64*FSTR + r*FSTR + c8)*2),
                   "l"(g_vh + (size_t)(b*SEQ + kt*64 + r)*KVD + hk*HD + c8));
        }
    };
    int nkt = 2*bx + 2;
    load_kv(0, 0);
    asm volatile("cp.async.commit_group;");

    int my_last = 2*bx + (w >= 4 ? 1 : 0);
    float m0 = -1.0e30f, m1 = -1.0e30f, l0 = 0.f, l1 = 0.f;
    float o[8][4] = {};
    const float SCALE = 0.18033688011112042f;

    unsigned qBase = smb + ((FSM_Q + (16*w + lrow)*FSTR) + lcol8)*2;

    for (int kt = 0; kt < nkt; kt++) {
        int bf = kt & 1;
        if (kt + 1 < nkt) {
            load_kv(kt + 1, bf ^ 1);
            asm volatile("cp.async.commit_group;");
            asm volatile("cp.async.wait_group 1;");
        } else {
            asm volatile("cp.async.wait_group 0;");
        }
        __syncthreads();

        if (kt <= my_last) {
            unsigned kBase = smb + ((FSM_K + bf*64*FSTR + lrow*FSTR) + lcol8)*2;
            unsigned vBase = smb + ((FSM_V + bf*64*FSTR + lrow*FSTR) + lcol8)*2;

            float s[8][4] = {};
            #pragma unroll
            for (int ks = 0; ks < 4; ks++) {
                unsigned af[4], kb[4][4];
                LDSM4(af, qBase + ks*32);
                #pragma unroll
                for (int j2 = 0; j2 < 4; j2++)
                    LDSM4(kb[j2], kBase + (j2*16*FSTR)*2 + ks*32);
                #pragma unroll
                for (int j = 0; j < 8; j++)
                    MMA_F16(s[j], af, kb[j>>1][j&1], kb[j>>1][(j&1)+2]);
            }
            if (kt == my_last) {
                int r0 = q0 + 16*w + g, r1 = r0 + 8;
                #pragma unroll
                for (int j = 0; j < 8; j++) {
                    int cg = kt*64 + j*8 + 2*tg;
                    s[j][0] = (cg   > r0) ? -1.0e30f : s[j][0]*SCALE;
                    s[j][1] = (cg+1 > r0) ? -1.0e30f : s[j][1]*SCALE;
                    s[j][2] = (cg   > r1) ? -1.0e30f : s[j][2]*SCALE;
                    s[j][3] = (cg+1 > r1) ? -1.0e30f : s[j][3]*SCALE;
                }
            } else {
                #pragma unroll
                for (int j = 0; j < 8; j++)
                    #pragma unroll
                    for (int q = 0; q < 4; q++) s[j][q] *= SCALE;
            }
            float mx0 = -1.0e30f, mx1 = -1.0e30f;
            #pragma unroll
            for (int j = 0; j < 8; j++) {
                mx0 = fmaxf(mx0, fmaxf(s[j][0], s[j][1]));
                mx1 = fmaxf(mx1, fmaxf(s[j][2], s[j][3]));
            }
            mx0 = fmaxf(mx0, __shfl_xor_sync(0xffffffffu, mx0, 1));
            mx0 = fmaxf(mx0, __shfl_xor_sync(0xffffffffu, mx0, 2));
            mx1 = fmaxf(mx1, __shfl_xor_sync(0xffffffffu, mx1, 1));
            mx1 = fmaxf(mx1, __shfl_xor_sync(0xffffffffu, mx1, 2));
            float mn0 = fmaxf(m0, mx0), mn1 = fmaxf(m1, mx1);
            float c0 = exp2f(m0 - mn0), c1 = exp2f(m1 - mn1);
            float rs0 = 0.f, rs1 = 0.f;
            #pragma unroll
            for (int j = 0; j < 8; j++) {
                s[j][0] = exp2f(s[j][0] - mn0); s[j][1] = exp2f(s[j][1] - mn0);
                s[j][2] = exp2f(s[j][2] - mn1); s[j][3] = exp2f(s[j][3] - mn1);
                rs0 += s[j][0] + s[j][1];
                rs1 += s[j][2] + s[j][3];
            }
            rs0 += __shfl_xor_sync(0xffffffffu, rs0, 1);
            rs0 += __shfl_xor_sync(0xffffffffu, rs0, 2);
            rs1 += __shfl_xor_sync(0xffffffffu, rs1, 1);
            rs1 += __shfl_xor_sync(0xffffffffu, rs1, 2);
            l0 = l0*c0 + rs0; l1 = l1*c1 + rs1;
            m0 = mn0; m1 = mn1;
            #pragma unroll
            for (int j = 0; j < 8; j++) {
                o[j][0] *= c0; o[j][1] *= c0;
                o[j][2] *= c1; o[j][3] *= c1;
            }
            #pragma unroll
            for (int kk = 0; kk < 4; kk++) {
                __half2 p0 = __floats2half2_rn(s[2*kk  ][0], s[2*kk  ][1]);
                __half2 p1 = __floats2half2_rn(s[2*kk  ][2], s[2*kk  ][3]);
                __half2 p2 = __floats2half2_rn(s[2*kk+1][0], s[2*kk+1][1]);
                __half2 p3 = __floats2half2_rn(s[2*kk+1][2], s[2*kk+1][3]);
                unsigned pa[4] = { *(unsigned*)&p0, *(unsigned*)&p1,
                                   *(unsigned*)&p2, *(unsigned*)&p3 };
                #pragma unroll
                for (int j2 = 0; j2 < 4; j2++) {
                    unsigned vb[4];
                    LDSM4T(vb, vBase + (kk*16*FSTR + j2*16)*2);
                    MMA_F16(o[2*j2  ], pa, vb[0], vb[1]);
                    MMA_F16(o[2*j2+1], pa, vb[2], vb[3]);
                }
            }
        }
        __syncthreads();
    }

    float i0 = 1.0f / l0, i1 = 1.0f / l1;
    size_t r0b = (size_t)(b*SEQ + q0 + 16*w + g    )*DIMX + h*HD;
    size_t r1b = (size_t)(b*SEQ + q0 + 16*w + g + 8)*DIMX + h*HD;
    #pragma unroll
    for (int j = 0; j < 8; j++) {
        int col = j*8 + 2*tg;
        *(__half2*)&g_attnh[r0b + col] = __floats2half2_rn(o[j][0]*i0, o[j][1]*i0);
        *(__half2*)&g_attnh[r1b + col] = __floats2half2_rn(o[j][2]*i1, o[j][3]*i1);
    }
}

// ---------------- router ----------------
__global__ void router_kernel(const float* __restrict__ wg) {
    int warp = (blockIdx.x*blockDim.x + threadIdx.x) >> 5;
    int lane = threadIdx.x & 31;
    if (warp >= TKN) return;
    int t = warp;
    float acc[NE] = {};
    const __half* hr = g_h2h + (size_t)t*DIMX;
    for (int d = lane; d < DIMX; d += 32) {
        float hv = __half2float(hr[d]);
        const float* wr = wg + (size_t)d*NE;
        #pragma unroll
        for (int e = 0; e < NE; e++) acc[e] += hv * wr[e];
    }
    #pragma unroll
    for (int e = 0; e < NE; e++)
        #pragma unroll
        for (int off = 16; off > 0; off >>= 1)
            acc[e] += __shfl_xor_sync(0xffffffffu, acc[e], off);
    if (lane == 0) {
        int e0 = 0; float v0 = acc[0];
        #pragma unroll
        for (int e = 1; e < NE; e++) if (acc[e] > v0) { v0 = acc[e]; e0 = e; }
        int e1 = -1; float v1 = -3.4e38f;
        #pragma unroll
        for (int e = 0; e < NE; e++) if (e != e0 && acc[e] > v1) { v1 = acc[e]; e1 = e; }
        float ex = expf(v1 - v0);
        float den = 1.0f + ex;
        float gg0 = 1.0f/den, gg1 = ex/den;
        atomicAdd(&g_counts[e0], 1); atomicAdd(&g_counts[e1], 1);
        int p0 = atomicAdd(&g_ecnt[e0], 1);
        g_tok[e0*TKN+p0] = t; g_gate[e0*TKN+p0] = gg0; g_dest[e0*TKN+p0] = t;
        int p1 = atomicAdd(&g_ecnt[e1], 1);
        g_tok[e1*TKN+p1] = t; g_gate[e1*TKN+p1] = gg1; g_dest[e1*TKN+p1] = TKN + t;
    }
}

// combine + lb loss (block 0 thread 0 writes the trailing scalar)
__global__ void combine_kernel(float* __restrict__ out, int out_size) {
    int i = blockIdx.x*256 + threadIdx.x;
    out[i] = g_x1[i] + g_part[i] + g_part[TKN*DIMX + i];
    if (blockIdx.x == 0 && threadIdx.x == 0) {
        float tot = 0.f;
        for (int e = 0; e < NE; e++) tot += (float)g_counts[e];
        float loss = 0.f;
        for (int e = 0; e < NE; e++) {
            float cn = (float)g_counts[e]/tot - 1.0f/NE;
            loss += cn*cn;
        }
        out[out_size - 1] = loss / NE;
    }
}

// ---------------- launch ----------------
extern "C" void kernel_launch(void* const* d_in, const int* in_sizes, int n_in,
                              void* d_out, int out_size) {
    const float* x    = (const float*)d_in[0];
    const float* wq   = (const float*)d_in[1];
    const float* wk   = (const float*)d_in[2];
    const float* wv   = (const float*)d_in[3];
    const float* wo   = (const float*)d_in[4];
    const float* wg   = (const float*)d_in[5];
    const float* w1   = (const float*)d_in[6];
    const float* w2   = (const float*)d_in[7];
    const float* ln1g = (const float*)d_in[8];
    const float* ln1b = (const float*)d_in[9];
    const float* ln2g = (const float*)d_in[10];
    const float* ln2b = (const float*)d_in[11];
    float* out = (float*)d_out;

    float *p_x1;
    __half *p_h1h, *p_attnh, *p_h2h, *p_wo16;
    cudaGetSymbolAddress((void**)&p_x1,   g_x1);
    cudaGetSymbolAddress((void**)&p_h1h,  g_h1h);
    cudaGetSymbolAddress((void**)&p_attnh,g_attnh);
    cudaGetSymbolAddress((void**)&p_h2h,  g_h2h);
    cudaGetSymbolAddress((void**)&p_wo16, g_wo16);

    static int attr_set = 0;
    if (!attr_set) {
        cudaFuncSetAttribute(attn_f16_kernel,
                             cudaFuncAttributeMaxDynamicSharedMemorySize, FSM_TOT);
        cudaFuncSetAttribute(hgemm<1>, cudaFuncAttributeMaxDynamicSharedMemorySize, SMEMB);
        cudaFuncSetAttribute(hgemm<2>, cudaFuncAttributeMaxDynamicSharedMemorySize, SMEMB);
        cudaFuncSetAttribute(hgemm<3>, cudaFuncAttributeMaxDynamicSharedMemorySize, SMEMB);
        cudaFuncSetAttribute(qkv_cvt_kernel, cudaFuncAttributeMaxDynamicSharedMemorySize, SMEMB);
        attr_set = 1;
    }

    cvt_dense_kernel<<<1280, 256>>>(wq, wk, wv, wo);
    ln_kernel<<<TKN, 256>>>(x, ln1g, ln1b, p_h1h);

    // QKV GEMM + w1/w2 convert overlapped in one launch
    qkv_cvt_kernel<<<QKV_BLKS + CVT_BLKS, 256, SMEMB>>>(p_h1h, w1, w2);

    rope_kernel<<<(TKN*(NH+NKV)*32)/256, 256>>>();
    attn_f16_kernel<<<dim3(SEQ/128, NH, BATCH), 256, FSM_TOT>>>();

    hgemm<1><<<dim3(DIMX/128, TKN/128, 1), 256, SMEMB>>>(
        p_attnh, p_wo16, p_x1, x, TKN, DIMX, DIMX);
    ln_kernel<<<TKN, 256>>>(p_x1, ln2g, ln2b, p_h2h);

    router_kernel<<<TKN/8, 256>>>(wg);

    hgemm<2><<<dim3(TKN/128, FFX/128,  NE), 256, SMEMB>>>(
        nullptr, nullptr, nullptr, nullptr, TKN, FFX, DIMX);
    hgemm<3><<<dim3(TKN/128, DIMX/128, NE), 256, SMEMB>>>(
        nullptr, nullptr, nullptr, nullptr, TKN, DIMX, FFX);

    combine_kernel<<<(TKN*DIMX)/256, 256>>>(out, out_size);
}

// round 17
// speedup vs baseline: 1.1553x; 1.0037x over previous
#include <cuda_runtime.h>
#include <cuda_fp16.h>
#include <math.h>

#define TKN 2048
#define BATCH 2
#define SEQ 1024
#define DIMX 1024
#define NH 16
#define NKV 4
#define HD 64
#define KVD (NKV*HD)   // 256
#define NE 8
#define FFX 4096

// ---------------- scratch ----------------
__device__ float g_x1[TKN*DIMX];
__device__ float g_part[2*TKN*DIMX];
__device__ __half g_qh [TKN*DIMX];
__device__ __half g_kh [TKN*KVD];
__device__ __half g_vh [TKN*KVD];
__device__ __half g_h1h [TKN*DIMX];
__device__ __half g_attnh[TKN*DIMX];
__device__ __half g_h2h [TKN*DIMX];
__device__ __half g_hidh[(size_t)NE*TKN*FFX];
__device__ __half g_wq16[DIMX*DIMX];
__device__ __half g_wk16[DIMX*KVD];
__device__ __half g_wv16[DIMX*KVD];
__device__ __half g_wo16[DIMX*DIMX];
__device__ __half g_w116[(size_t)NE*DIMX*FFX];
__device__ __half g_w216[(size_t)NE*FFX*DIMX];
__device__ int   g_tok [NE*TKN];
__device__ float g_gate[NE*TKN];
__device__ int   g_dest[NE*TKN];
__device__ int   g_ecnt[NE];
__device__ int   g_counts[NE];

// ---------------- fp32 -> fp16 helpers ----------------
__device__ __forceinline__ void cvt8(const float* __restrict__ s, __half* __restrict__ d, int i) {
    float4 a = ((const float4*)s)[2*i];
    float4 b = ((const float4*)s)[2*i + 1];
    __half2 h0 = __floats2half2_rn(a.x, a.y);
    __half2 h1 = __floats2half2_rn(a.z, a.w);
    __half2 h2 = __floats2half2_rn(b.x, b.y);
    __half2 h3 = __floats2half2_rn(b.z, b.w);
    uint4 u;
    u.x = ((unsigned)__half_as_ushort(__high2half(h0)) << 16) | __half_as_ushort(__low2half(h0));
    u.y = ((unsigned)__half_as_ushort(__high2half(h1)) << 16) | __half_as_ushort(__low2half(h1));
    u.z = ((unsigned)__half_as_ushort(__high2half(h2)) << 16) | __half_as_ushort(__low2half(h2));
    u.w = ((unsigned)__half_as_ushort(__high2half(h3)) << 16) | __half_as_ushort(__low2half(h3));
    ((uint4*)d)[i] = u;
}

// dense weights (+ counter zero): ranges in 8-float units
#define DQ 131072
#define DK (DQ + 32768)
#define DV (DK + 32768)
#define DO (DV + 131072)     // 327680 = 1280 * 256
__global__ void cvt_dense_kernel(const float* __restrict__ wq, const float* __restrict__ wk,
                                 const float* __restrict__ wv, const float* __restrict__ wo) {
    int i = blockIdx.x*256 + threadIdx.x;
    if (blockIdx.x == 0 && threadIdx.x < NE) { g_ecnt[threadIdx.x] = 0; g_counts[threadIdx.x] = 0; }
    if (i < DQ)      cvt8(wq, g_wq16, i);
    else if (i < DK) cvt8(wk, g_wk16, i - DQ);
    else if (i < DV) cvt8(wv, g_wv16, i - DK);
    else             cvt8(wo, g_wo16, i - DV);
}

// ---------------- layernorm -> fp16 ----------------
__global__ void ln_kernel(const float* __restrict__ x, const float* __restrict__ g,
                          const float* __restrict__ b, __half* __restrict__ out) {
    int row = blockIdx.x;
    int tid = threadIdx.x;
    const float* xr = x + (size_t)row * DIMX;
    float v[4]; float s = 0.f;
    #pragma unroll
    for (int j = 0; j < 4; j++) { v[j] = xr[tid + 256*j]; s += v[j]; }
    __shared__ float red[8];
    #pragma unroll
    for (int o = 16; o > 0; o >>= 1) s += __shfl_xor_sync(0xffffffffu, s, o);
    if ((tid & 31) == 0) red[tid >> 5] = s;
    __syncthreads();
    float tot = red[0]+red[1]+red[2]+red[3]+red[4]+red[5]+red[6]+red[7];
    float mu = tot / DIMX;
    float sq = 0.f;
    #pragma unroll
    for (int j = 0; j < 4; j++) { float d = v[j]-mu; sq += d*d; }
    #pragma unroll
    for (int o = 16; o > 0; o >>= 1) sq += __shfl_xor_sync(0xffffffffu, sq, o);
    __syncthreads();
    if ((tid & 31) == 0) red[tid >> 5] = sq;
    __syncthreads();
    float vtot = red[0]+red[1]+red[2]+red[3]+red[4]+red[5]+red[6]+red[7];
    float rstd = rsqrtf(vtot / DIMX + 1e-5f);
    #pragma unroll
    for (int j = 0; j < 4; j++) {
        int d = tid + 256*j;
        out[(size_t)row*DIMX + d] = __float2half_rn((v[j]-mu)*rstd*g[d] + b[d]);
    }
}

// ---------------- shared mma macros ----------------
#define LDSM4(R, addr) \
    asm volatile("ldmatrix.sync.aligned.m8n8.x4.shared.b16 {%0,%1,%2,%3}, [%4];" \
        : "=r"(R[0]), "=r"(R[1]), "=r"(R[2]), "=r"(R[3]) : "r"(addr))
#define LDSM4T(R, addr) \
    asm volatile("ldmatrix.sync.aligned.m8n8.x4.trans.shared.b16 {%0,%1,%2,%3}, [%4];" \
        : "=r"(R[0]), "=r"(R[1]), "=r"(R[2]), "=r"(R[3]) : "r"(addr))
#define MMA_F16(C4, A4, B0, B1) \
    asm volatile("mma.sync.aligned.m16n8k16.row.col.f32.f16.f16.f32 " \
        "{%0,%1,%2,%3},{%4,%5,%6,%7},{%8,%9},{%0,%1,%2,%3};" \
        : "+f"(C4[0]), "+f"(C4[1]), "+f"(C4[2]), "+f"(C4[3]) \
        : "r"(A4[0]), "r"(A4[1]), "r"(A4[2]), "r"(A4[3]), "r"(B0), "r"(B1))

#define ASTG (128*40)
#define BSTG (32*136)
#define BBASE (3*ASTG)
#define SMEMB ((BBASE + 3*BSTG)*2)

// ---------------- dense fp16 GEMM (128x128, 8 warps 64x32, 3-stage) ----------------
// MODE 1: C=A@B+resid (fp32 out)
template<int MODE>
__global__ __launch_bounds__(256, 2)
void hgemm(const __half* __restrict__ A, const __half* __restrict__ Bm,
           float* __restrict__ C, const float* __restrict__ resid,
           int M, int N, int K) {
    extern __shared__ __half smh[];
    int ldB = N, ldC = N;
    int n0 = blockIdx.x * 128, m0 = blockIdx.y * 128;
    int cbase = n0;
    int tid = threadIdx.x;
    int warp = tid >> 5, lane = tid & 31;
    int wm = warp >> 2, wn = warp & 3;
    int g = lane >> 2, tg = lane & 3;

    const __half* aSrc[2]; unsigned aOff[2];
    #pragma unroll
    for (int p = 0; p < 2; p++) {
        int id = tid + p*256;
        int r = id >> 2, c8 = (id & 3) << 3;
        aSrc[p] = A + (size_t)(m0 + r)*K + c8;
        aOff[p] = (r*40 + c8)*2;
    }
    const __half* bSrc[2]; unsigned bOff[2];
    #pragma unroll
    for (int p = 0; p < 2; p++) {
        int id = tid + p*256;
        int r = id >> 4, c8 = (id & 15) << 3;
        bSrc[p] = Bm + (size_t)r*ldB + cbase + c8;
        bOff[p] = (BBASE + r*136 + c8)*2;
    }
    unsigned smb = (unsigned)__cvta_generic_to_shared(smh);

    auto load_stage = [&](int s, int kt) {
        int k0 = kt*32;
        #pragma unroll
        for (int p = 0; p < 2; p++)
            asm volatile("cp.async.cg.shared.global [%0], [%1], 16;"
                :: "r"(smb + s*(ASTG*2) + aOff[p]), "l"(aSrc[p] + k0));
        #pragma unroll
        for (int p = 0; p < 2; p++)
            asm volatile("cp.async.cg.shared.global [%0], [%1], 16;"
                :: "r"(smb + s*(BSTG*2) + bOff[p]), "l"(bSrc[p] + (size_t)k0*ldB));
        asm volatile("cp.async.commit_group;");
    };

    unsigned aBase = smb + ((wm*64 + ((lane>>3)&1)*8 + (lane&7))*40 + (lane>>4)*8)*2;
    unsigned bBase = smb + BBASE*2 + ((((lane>>3)&1)*8 + (lane&7))*136 + wn*32 + (lane>>4)*8)*2;

    float c[4][4][4] = {};
    int nk = K / 32;
    load_stage(0, 0);
    load_stage(1, 1);
    for (int kt = 0; kt < nk; kt++) {
        int s = kt % 3;
        if (kt < nk - 1) asm volatile("cp.async.wait_group 1;");
        else             asm volatile("cp.async.wait_group 0;");
        __syncthreads();
        unsigned aS = aBase + s*(ASTG*2);
        unsigned bS = bBase + s*(BSTG*2);
        #pragma unroll
        for (int ks = 0; ks < 2; ks++) {
            unsigned af[4][4], bq[2][4];
            #pragma unroll
            for (int i = 0; i < 4; i++)
                LDSM4(af[i], aS + (i*16*40 + ks*16)*2);
            #pragma unroll
            for (int jp = 0; jp < 2; jp++)
                LDSM4T(bq[jp], bS + (ks*16*136 + jp*16)*2);
            #pragma unroll
            for (int i = 0; i < 4; i++)
                #pragma unroll
                for (int j = 0; j < 4; j++)
                    MMA_F16(c[i][j], af[i], bq[j>>1][(j&1)*2], bq[j>>1][(j&1)*2+1]);
        }
        if (kt + 2 < nk) load_stage((kt+2) % 3, kt+2);
    }

    #pragma unroll
    for (int i = 0; i < 4; i++) {
        #pragma unroll
        for (int half = 0; half < 2; half++) {
            int r = m0 + wm*64 + i*16 + g + half*8;
            #pragma unroll
            for (int j = 0; j < 4; j++) {
                float v0 = c[i][j][half*2 + 0];
                float v1 = c[i][j][half*2 + 1];
                int col = cbase + wn*32 + j*8 + 2*tg;
                float2 rr = *(const float2*)&resid[(size_t)r*ldC + col];
                *(float2*)&C[(size_t)r*ldC + col] = make_float2(v0+rr.x, v1+rr.y);
            }
        }
    }
}

// ---------------- MoE fp16 GEMM (128x128, 4 warps 64x64, occ 2, 3-stage) ----------------
// MODE 2: up (gather rows via g_tok, GELU, fp16 out)  MODE 3: down (scatter*gate, fp32)
// m-tile on blockIdx.x (fastest) for B-slab L2 sharing.
template<int MODE>
__global__ __launch_bounds__(128, 2)
void hgemm_moe(int N, int K) {
    extern __shared__ __half smh[];
    int e = blockIdx.z;
    int M = g_ecnt[e];
    int m0 = blockIdx.x * 128, n0 = blockIdx.y * 128;
    if (m0 >= M) return;
    const __half* A; const __half* Bm; __half* C16 = nullptr; int ldC = N;
    if (MODE == 2) { A = g_h2h; Bm = g_w116 + (size_t)e*DIMX*FFX; C16 = g_hidh + (size_t)e*TKN*FFX; }
    else           { A = g_hidh + (size_t)e*TKN*FFX; Bm = g_w216 + (size_t)e*FFX*DIMX; ldC = DIMX; }
    int tid = threadIdx.x;
    int warp = tid >> 5, lane = tid & 31;
    int wm = warp >> 1, wn = warp & 1;   // 2x2 warps, warp tile 64x64
    int g = lane >> 2, tg = lane & 3;

    const __half* aSrc[4]; int aSz[4]; unsigned aOff[4];
    #pragma unroll
    for (int p = 0; p < 4; p++) {
        int id = tid + p*128;
        int r = id >> 2, c8 = (id & 3) << 3;
        int rg = m0 + r;
        bool valid = rg < M;
        const __half* ptr;
        if (MODE == 2) {
            int t = valid ? g_tok[e*TKN + rg] : 0;
            ptr = A + (size_t)t*K + c8;
        } else {
            ptr = A + (size_t)(valid ? rg : 0)*K + c8;
        }
        aSrc[p] = ptr; aSz[p] = valid ? 16 : 0;
        aOff[p] = (r*40 + c8)*2;
    }
    const __half* bSrc[4]; unsigned bOff[4];
    #pragma unroll
    for (int p = 0; p < 4; p++) {
        int id = tid + p*128;
        int r = id >> 4, c8 = (id & 15) << 3;
        bSrc[p] = Bm + (size_t)r*N + n0 + c8;
        bOff[p] = (BBASE + r*136 + c8)*2;
    }
    unsigned smb = (unsigned)__cvta_generic_to_shared(smh);

    auto load_stage = [&](int s, int kt) {
        int k0 = kt*32;
        #pragma unroll
        for (int p = 0; p < 4; p++)
            asm volatile("cp.async.cg.shared.global [%0], [%1], 16, %2;"
                :: "r"(smb + s*(ASTG*2) + aOff[p]), "l"(aSrc[p] + k0), "r"(aSz[p]));
        #pragma unroll
        for (int p = 0; p < 4; p++)
            asm volatile("cp.async.cg.shared.global [%0], [%1], 16;"
                :: "r"(smb + s*(BSTG*2) + bOff[p]), "l"(bSrc[p] + (size_t)k0*N));
        asm volatile("cp.async.commit_group;");
    };

    unsigned aBase = smb + ((wm*64 + ((lane>>3)&1)*8 + (lane&7))*40 + (lane>>4)*8)*2;
    unsigned bBase = smb + BBASE*2 + ((((lane>>3)&1)*8 + (lane&7))*136 + wn*64 + (lane>>4)*8)*2;

    float c[4][8][4] = {};
    int nk = K / 32;
    load_stage(0, 0);
    load_stage(1, 1);
    for (int kt = 0; kt < nk; kt++) {
        int s = kt % 3;
        if (kt < nk - 1) asm volatile("cp.async.wait_group 1;");
        else             asm volatile("cp.async.wait_group 0;");
        __syncthreads();
        unsigned aS = aBase + s*(ASTG*2);
        unsigned bS = bBase + s*(BSTG*2);
        #pragma unroll
        for (int ks = 0; ks < 2; ks++) {
            unsigned af[4][4], bq[4][4];
            #pragma unroll
            for (int i = 0; i < 4; i++)
                LDSM4(af[i], aS + (i*16*40 + ks*16)*2);
            #pragma unroll
            for (int jp = 0; jp < 4; jp++)
                LDSM4T(bq[jp], bS + (ks*16*136 + jp*16)*2);
            #pragma unroll
            for (int i = 0; i < 4; i++)
                #pragma unroll
                for (int j = 0; j < 8; j++)
                    MMA_F16(c[i][j], af[i], bq[j>>1][(j&1)*2], bq[j>>1][(j&1)*2+1]);
        }
        if (kt + 2 < nk) load_stage((kt+2) % 3, kt+2);
    }

    #pragma unroll
    for (int i = 0; i < 4; i++) {
        #pragma unroll
        for (int half = 0; half < 2; half++) {
            int r = m0 + wm*64 + i*16 + g + half*8;
            if (r >= M) continue;
            #pragma unroll
            for (int j = 0; j < 8; j++) {
                float v0 = c[i][j][half*2 + 0];
                float v1 = c[i][j][half*2 + 1];
                int col = n0 + wn*64 + j*8 + 2*tg;
                if (MODE == 2) {
                    float o0 = 0.5f*v0*(1.0f + erff(v0*0.70710678118654752f));
                    float o1 = 0.5f*v1*(1.0f + erff(v1*0.70710678118654752f));
                    *(__half2*)&C16[(size_t)r*ldC + col] = __floats2half2_rn(o0, o1);
                } else {
                    int p = g_dest[e*TKN + r];
                    float s = g_gate[e*TKN + r];
                    *(float2*)&g_part[(size_t)p*DIMX + col] = make_float2(s*v0, s*v1);
                }
            }
        }
    }
}

// ---------------- fused QKV GEMM + w1/w2 convert (single launch overlap) ----------------
#define QKV_BLKS 192
#define CVT_UNITS_W (NE*DIMX*FFX/8)
#define CVT_BLKS 4096

__global__ __launch_bounds__(256, 2)
void qkv_cvt_kernel(const __half* __restrict__ A,
                    const float* __restrict__ w1, const float* __restrict__ w2) {
    if (blockIdx.x >= QKV_BLKS) {
        int b2 = blockIdx.x - QKV_BLKS;
        #pragma unroll
        for (int p = 0; p < 8; p++) {
            int u = b2*2048 + p*256 + threadIdx.x;
            if (u < CVT_UNITS_W) cvt8(w1, g_w116, u);
            else                 cvt8(w2, g_w216, u - CVT_UNITS_W);
        }
        return;
    }
    extern __shared__ __half smh[];
    int gid = blockIdx.x;
    int n0 = (gid % 12) * 128;
    int m0 = (gid / 12) * 128;
    const __half* Bm; __half* C16; int ldB, ldC, cbase;
    if (n0 < DIMX)            { Bm = g_wq16; ldB = DIMX; C16 = g_qh; ldC = DIMX; cbase = n0; }
    else if (n0 < DIMX + KVD) { Bm = g_wk16; ldB = KVD;  C16 = g_kh; ldC = KVD;  cbase = n0 - DIMX; }
    else                      { Bm = g_wv16; ldB = KVD;  C16 = g_vh; ldC = KVD;  cbase = n0 - DIMX - KVD; }
    const int K = DIMX;
    int tid = threadIdx.x;
    int warp = tid >> 5, lane = tid & 31;
    int wm = warp >> 2, wn = warp & 3;
    int g = lane >> 2, tg = lane & 3;

    const __half* aSrc[2]; unsigned aOff[2];
    #pragma unroll
    for (int p = 0; p < 2; p++) {
        int id = tid + p*256;
        int r = id >> 2, c8 = (id & 3) << 3;
        aSrc[p] = A + (size_t)(m0 + r)*K + c8;
        aOff[p] = (r*40 + c8)*2;
    }
    const __half* bSrc[2]; unsigned bOff[2];
    #pragma unroll
    for (int p = 0; p < 2; p++) {
        int id = tid + p*256;
        int r = id >> 4, c8 = (id & 15) << 3;
        bSrc[p] = Bm + (size_t)r*ldB + cbase + c8;
        bOff[p] = (BBASE + r*136 + c8)*2;
    }
    unsigned smb = (unsigned)__cvta_generic_to_shared(smh);

    auto load_stage = [&](int s, int kt) {
        int k0 = kt*32;
        #pragma unroll
        for (int p = 0; p < 2; p++)
            asm volatile("cp.async.cg.shared.global [%0], [%1], 16;"
                :: "r"(smb + s*(ASTG*2) + aOff[p]), "l"(aSrc[p] + k0));
        #pragma unroll
        for (int p = 0; p < 2; p++)
            asm volatile("cp.async.cg.shared.global [%0], [%1], 16;"
                :: "r"(smb + s*(BSTG*2) + bOff[p]), "l"(bSrc[p] + (size_t)k0*ldB));
        asm volatile("cp.async.commit_group;");
    };

    unsigned aBase = smb + ((wm*64 + ((lane>>3)&1)*8 + (lane&7))*40 + (lane>>4)*8)*2;
    unsigned bBase = smb + BBASE*2 + ((((lane>>3)&1)*8 + (lane&7))*136 + wn*32 + (lane>>4)*8)*2;

    float c[4][4][4] = {};
    int nk = K / 32;
    load_stage(0, 0);
    load_stage(1, 1);
    for (int kt = 0; kt < nk; kt++) {
        int s = kt % 3;
        if (kt < nk - 1) asm volatile("cp.async.wait_group 1;");
        else             asm volatile("cp.async.wait_group 0;");
        __syncthreads();
        unsigned aS = aBase + s*(ASTG*2);
        unsigned bS = bBase + s*(BSTG*2);
        #pragma unroll
        for (int ks = 0; ks < 2; ks++) {
            unsigned af[4][4], bq[2][4];
            #pragma unroll
            for (int i = 0; i < 4; i++)
                LDSM4(af[i], aS + (i*16*40 + ks*16)*2);
            #pragma unroll
            for (int jp = 0; jp < 2; jp++)
                LDSM4T(bq[jp], bS + (ks*16*136 + jp*16)*2);
            #pragma unroll
            for (int i = 0; i < 4; i++)
                #pragma unroll
                for (int j = 0; j < 4; j++)
                    MMA_F16(c[i][j], af[i], bq[j>>1][(j&1)*2], bq[j>>1][(j&1)*2+1]);
        }
        if (kt + 2 < nk) load_stage((kt+2) % 3, kt+2);
    }

    #pragma unroll
    for (int i = 0; i < 4; i++) {
        #pragma unroll
        for (int half = 0; half < 2; half++) {
            int r = m0 + wm*64 + i*16 + g + half*8;
            #pragma unroll
            for (int j = 0; j < 4; j++) {
                int col = cbase + wn*32 + j*8 + 2*tg;
                *(__half2*)&C16[(size_t)r*ldC + col] =
                    __floats2half2_rn(c[i][j][half*2 + 0], c[i][j][half*2 + 1]);
            }
        }
    }
}

// ---------------- RoPE (fp16 in place) ----------------
__global__ void rope_kernel() {
    int idx = blockIdx.x*blockDim.x + threadIdx.x;
    const int totq = TKN*NH*32;
    const int totk = TKN*NKV*32;
    __half* arr; size_t base; int t, i;
    if (idx < totq) {
        arr = g_qh; i = idx & 31; int rest = idx >> 5;
        int head = rest % NH; t = rest / NH;
        base = (size_t)t*DIMX + head*HD;
    } else {
        idx -= totq;
        if (idx >= totk) return;
        arr = g_kh; i = idx & 31; int rest = idx >> 5;
        int head = rest % NKV; t = rest / NKV;
        base = (size_t)t*KVD + head*HD;
    }
    int pos = t % SEQ;
    float freq = expf(-(float)(2*i) * (9.210340371976184f / 64.0f));
    float ang = (float)pos * freq;
    float cs = cosf(ang), sn = sinf(ang);
    float x1 = __half2float(arr[base + i]), x2 = __half2float(arr[base + 32 + i]);
    arr[base + i]      = __float2half_rn(x1*cs - x2*sn);
    arr[base + 32 + i] = __float2half_rn(x2*cs + x1*sn);
}

// ---------------- fp16 tensor-core flash attention (shuffle-free P@V) ----------------
#define FSTR 72
#define FSM_Q 0
#define FSM_K (128*FSTR)
#define FSM_V (FSM_K + 2*64*FSTR)
#define FSM_TOT ((FSM_V + 2*64*FSTR)*2)

__global__ __launch_bounds__(256, 2)
void attn_f16_kernel() {
    extern __shared__ __half smA[];
    int bx = blockIdx.x, h = blockIdx.y, b = blockIdx.z;
    int hk = h >> 2;
    int q0 = bx * 128;
    int tid = threadIdx.x, w = tid >> 5, lane = tid & 31;
    int g = lane >> 2, tg = lane & 3;
    unsigned smb = (unsigned)__cvta_generic_to_shared(smA);
    int lrow = (lane & 7) + ((lane >> 3) & 1)*8;
    int lcol8 = (lane >> 4)*8;

    #pragma unroll
    for (int p = 0; p < 4; p++) {
        int id = tid + p*256;
        int r = id >> 3, c8 = (id & 7) << 3;
        asm volatile("cp.async.cg.shared.global [%0], [%1], 16;"
            :: "r"(smb + (FSM_Q + r*FSTR + c8)*2),
               "l"(g_qh + (size_t)(b*SEQ + q0 + r)*DIMX + h*HD + c8));
    }
    auto load_kv = [&](int kt, int bf) {
        #pragma unroll
        for (int p = 0; p < 2; p++) {
            int id = tid + p*256;
            int r = id >> 3, c8 = (id & 7) << 3;
            asm volatile("cp.async.cg.shared.global [%0], [%1], 16;"
                :: "r"(smb + (FSM_K + bf*64*FSTR + r*FSTR + c8)*2),
                   "l"(g_kh + (size_t)(b*SEQ + kt*64 + r)*KVD + hk*HD + c8));
            asm volatile("cp.async.cg.shared.global [%0], [%1], 16;"
                :: "r"(smb + (FSM_V + bf*64*FSTR + r*FSTR + c8)*2),
                   "l"(g_vh + (size_t)(b*SEQ + kt*64 + r)*KVD + hk*HD + c8));
        }
    };
    int nkt = 2*bx + 2;
    load_kv(0, 0);
    asm volatile("cp.async.commit_group;");

    int my_last = 2*bx + (w >= 4 ? 1 : 0);
    float m0 = -1.0e30f, m1 = -1.0e30f, l0 = 0.f, l1 = 0.f;
    float o[8][4] = {};
    const float SCALE = 0.18033688011112042f;

    unsigned qBase = smb + ((FSM_Q + (16*w + lrow)*FSTR) + lcol8)*2;

    for (int kt = 0; kt < nkt; kt++) {
        int bf = kt & 1;
        if (kt + 1 < nkt) {
            load_kv(kt + 1, bf ^ 1);
            asm volatile("cp.async.commit_group;");
            asm volatile("cp.async.wait_group 1;");
        } else {
            asm volatile("cp.async.wait_group 0;");
        }
        __syncthreads();

        if (kt <= my_last) {
            unsigned kBase = smb + ((FSM_K + bf*64*FSTR + lrow*FSTR) + lcol8)*2;
            unsigned vBase = smb + ((FSM_V + bf*64*FSTR + lrow*FSTR) + lcol8)*2;

            float s[8][4] = {};
            #pragma unroll
            for (int ks = 0; ks < 4; ks++) {
                unsigned af[4], kb[4][4];
                LDSM4(af, qBase + ks*32);
                #pragma unroll
                for (int j2 = 0; j2 < 4; j2++)
                    LDSM4(kb[j2], kBase + (j2*16*FSTR)*2 + ks*32);
                #pragma unroll
                for (int j = 0; j < 8; j++)
                    MMA_F16(s[j], af, kb[j>>1][j&1], kb[j>>1][(j&1)+2]);
            }
            if (kt == my_last) {
                int r0 = q0 + 16*w + g, r1 = r0 + 8;
                #pragma unroll
                for (int j = 0; j < 8; j++) {
                    int cg = kt*64 + j*8 + 2*tg;
                    s[j][0] = (cg   > r0) ? -1.0e30f : s[j][0]*SCALE;
                    s[j][1] = (cg+1 > r0) ? -1.0e30f : s[j][1]*SCALE;
                    s[j][2] = (cg   > r1) ? -1.0e30f : s[j][2]*SCALE;
                    s[j][3] = (cg+1 > r1) ? -1.0e30f : s[j][3]*SCALE;
                }
            } else {
                #pragma unroll
                for (int j = 0; j < 8; j++)
                    #pragma unroll
                    for (int q = 0; q < 4; q++) s[j][q] *= SCALE;
            }
            float mx0 = -1.0e30f, mx1 = -1.0e30f;
            #pragma unroll
            for (int j = 0; j < 8; j++) {
                mx0 = fmaxf(mx0, fmaxf(s[j][0], s[j][1]));
                mx1 = fmaxf(mx1, fmaxf(s[j][2], s[j][3]));
            }
            mx0 = fmaxf(mx0, __shfl_xor_sync(0xffffffffu, mx0, 1));
            mx0 = fmaxf(mx0, __shfl_xor_sync(0xffffffffu, mx0, 2));
            mx1 = fmaxf(mx1, __shfl_xor_sync(0xffffffffu, mx1, 1));
            mx1 = fmaxf(mx1, __shfl_xor_sync(0xffffffffu, mx1, 2));
            float mn0 = fmaxf(m0, mx0), mn1 = fmaxf(m1, mx1);
            float c0 = exp2f(m0 - mn0), c1 = exp2f(m1 - mn1);
            float rs0 = 0.f, rs1 = 0.f;
            #pragma unroll
            for (int j = 0; j < 8; j++) {
                s[j][0] = exp2f(s[j][0] - mn0); s[j][1] = exp2f(s[j][1] - mn0);
                s[j][2] = exp2f(s[j][2] - mn1); s[j][3] = exp2f(s[j][3] - mn1);
                rs0 += s[j][0] + s[j][1];
                rs1 += s[j][2] + s[j][3];
            }
            rs0 += __shfl_xor_sync(0xffffffffu, rs0, 1);
            rs0 += __shfl_xor_sync(0xffffffffu, rs0, 2);
            rs1 += __shfl_xor_sync(0xffffffffu, rs1, 1);
            rs1 += __shfl_xor_sync(0xffffffffu, rs1, 2);
            l0 = l0*c0 + rs0; l1 = l1*c1 + rs1;
            m0 = mn0; m1 = mn1;
            #pragma unroll
            for (int j = 0; j < 8; j++) {
                o[j][0] *= c0; o[j][1] *= c0;
                o[j][2] *= c1; o[j][3] *= c1;
            }
            #pragma unroll
            for (int kk = 0; kk < 4; kk++) {
                __half2 p0 = __floats2half2_rn(s[2*kk  ][0], s[2*kk  ][1]);
                __half2 p1 = __floats2half2_rn(s[2*kk  ][2], s[2*kk  ][3]);
                __half2 p2 = __floats2half2_rn(s[2*kk+1][0], s[2*kk+1][1]);
                __half2 p3 = __floats2half2_rn(s[2*kk+1][2], s[2*kk+1][3]);
                unsigned pa[4] = { *(unsigned*)&p0, *(unsigned*)&p1,
                                   *(unsigned*)&p2, *(unsigned*)&p3 };
                #pragma unroll
                for (int j2 = 0; j2 < 4; j2++) {
                    unsigned vb[4];
                    LDSM4T(vb, vBase + (kk*16*FSTR + j2*16)*2);
                    MMA_F16(o[2*j2  ], pa, vb[0], vb[1]);
                    MMA_F16(o[2*j2+1], pa, vb[2], vb[3]);
                }
            }
        }
        __syncthreads();
    }

    float i0 = 1.0f / l0, i1 = 1.0f / l1;
    size_t r0b = (size_t)(b*SEQ + q0 + 16*w + g    )*DIMX + h*HD;
    size_t r1b = (size_t)(b*SEQ + q0 + 16*w + g + 8)*DIMX + h*HD;
    #pragma unroll
    for (int j = 0; j < 8; j++) {
        int col = j*8 + 2*tg;
        *(__half2*)&g_attnh[r0b + col] = __floats2half2_rn(o[j][0]*i0, o[j][1]*i0);
        *(__half2*)&g_attnh[r1b + col] = __floats2half2_rn(o[j][2]*i1, o[j][3]*i1);
    }
}

// ---------------- router ----------------
__global__ void router_kernel(const float* __restrict__ wg) {
    int warp = (blockIdx.x*blockDim.x + threadIdx.x) >> 5;
    int lane = threadIdx.x & 31;
    if (warp >= TKN) return;
    int t = warp;
    float acc[NE] = {};
    const __half* hr = g_h2h + (size_t)t*DIMX;
    for (int d = lane; d < DIMX; d += 32) {
        float hv = __half2float(hr[d]);
        const float* wr = wg + (size_t)d*NE;
        #pragma unroll
        for (int e = 0; e < NE; e++) acc[e] += hv * wr[e];
    }
    #pragma unroll
    for (int e = 0; e < NE; e++)
        #pragma unroll
        for (int off = 16; off > 0; off >>= 1)
            acc[e] += __shfl_xor_sync(0xffffffffu, acc[e], off);
    if (lane == 0) {
        int e0 = 0; float v0 = acc[0];
        #pragma unroll
        for (int e = 1; e < NE; e++) if (acc[e] > v0) { v0 = acc[e]; e0 = e; }
        int e1 = -1; float v1 = -3.4e38f;
        #pragma unroll
        for (int e = 0; e < NE; e++) if (e != e0 && acc[e] > v1) { v1 = acc[e]; e1 = e; }
        float ex = expf(v1 - v0);
        float den = 1.0f + ex;
        float gg0 = 1.0f/den, gg1 = ex/den;
        atomicAdd(&g_counts[e0], 1); atomicAdd(&g_counts[e1], 1);
        int p0 = atomicAdd(&g_ecnt[e0], 1);
        g_tok[e0*TKN+p0] = t; g_gate[e0*TKN+p0] = gg0; g_dest[e0*TKN+p0] = t;
        int p1 = atomicAdd(&g_ecnt[e1], 1);
        g_tok[e1*TKN+p1] = t; g_gate[e1*TKN+p1] = gg1; g_dest[e1*TKN+p1] = TKN + t;
    }
}

// combine + lb loss
__global__ void combine_kernel(float* __restrict__ out, int out_size) {
    int i = blockIdx.x*256 + threadIdx.x;
    out[i] = g_x1[i] + g_part[i] + g_part[TKN*DIMX + i];
    if (blockIdx.x == 0 && threadIdx.x == 0) {
        float tot = 0.f;
        for (int e = 0; e < NE; e++) tot += (float)g_counts[e];
        float loss = 0.f;
        for (int e = 0; e < NE; e++) {
            float cn = (float)g_counts[e]/tot - 1.0f/NE;
            loss += cn*cn;
        }
        out[out_size - 1] = loss / NE;
    }
}

// ---------------- launch ----------------
extern "C" void kernel_launch(void* const* d_in, const int* in_sizes, int n_in,
                              void* d_out, int out_size) {
    const float* x    = (const float*)d_in[0];
    const float* wq   = (const float*)d_in[1];
    const float* wk   = (const float*)d_in[2];
    const float* wv   = (const float*)d_in[3];
    const float* wo   = (const float*)d_in[4];
    const float* wg   = (const float*)d_in[5];
    const float* w1   = (const float*)d_in[6];
    const float* w2   = (const float*)d_in[7];
    const float* ln1g = (const float*)d_in[8];
    const float* ln1b = (const float*)d_in[9];
    const float* ln2g = (const float*)d_in[10];
    const float* ln2b = (const float*)d_in[11];
    float* out = (float*)d_out;

    float *p_x1;
    __half *p_h1h, *p_attnh, *p_h2h, *p_wo16;
    cudaGetSymbolAddress((void**)&p_x1,   g_x1);
    cudaGetSymbolAddress((void**)&p_h1h,  g_h1h);
    cudaGetSymbolAddress((void**)&p_attnh,g_attnh);
    cudaGetSymbolAddress((void**)&p_h2h,  g_h2h);
    cudaGetSymbolAddress((void**)&p_wo16, g_wo16);

    static int attr_set = 0;
    if (!attr_set) {
        cudaFuncSetAttribute(attn_f16_kernel,
                             cudaFuncAttributeMaxDynamicSharedMemorySize, FSM_TOT);
        cudaFuncSetAttribute(hgemm<1>, cudaFuncAttributeMaxDynamicSharedMemorySize, SMEMB);
        cudaFuncSetAttribute(hgemm_moe<2>, cudaFuncAttributeMaxDynamicSharedMemorySize, SMEMB);
        cudaFuncSetAttribute(hgemm_moe<3>, cudaFuncAttributeMaxDynamicSharedMemorySize, SMEMB);
        cudaFuncSetAttribute(qkv_cvt_kernel, cudaFuncAttributeMaxDynamicSharedMemorySize, SMEMB);
        attr_set = 1;
    }

    cvt_dense_kernel<<<1280, 256>>>(wq, wk, wv, wo);
    ln_kernel<<<TKN, 256>>>(x, ln1g, ln1b, p_h1h);

    qkv_cvt_kernel<<<QKV_BLKS + CVT_BLKS, 256, SMEMB>>>(p_h1h, w1, w2);

    rope_kernel<<<(TKN*(NH+NKV)*32)/256, 256>>>();
    attn_f16_kernel<<<dim3(SEQ/128, NH, BATCH), 256, FSM_TOT>>>();

    hgemm<1><<<dim3(DIMX/128, TKN/128, 1), 256, SMEMB>>>(
        p_attnh, p_wo16, p_x1, x, TKN, DIMX, DIMX);
    ln_kernel<<<TKN, 256>>>(p_x1, ln2g, ln2b, p_h2h);

    router_kernel<<<TKN/8, 256>>>(wg);

    hgemm_moe<2><<<dim3(TKN/128, FFX/128,  NE), 128, SMEMB>>>(FFX, DIMX);
    hgemm_moe<3><<<dim3(TKN/128, DIMX/128, NE), 128, SMEMB>>>(DIMX, FFX);

    combine_kernel<<<(TKN*DIMX)/256, 256>>>(out, out_size);
}